// round 2
// baseline (speedup 1.0000x reference)
#include <cuda_runtime.h>
#include <math.h>

#define NJ   68
#define RES  32
#define NB   2048
#define NROWS 4096
#define DIMX 96
#define NSWEEPS 12
#define JAC_THREADS 512
#define JAC_SMEM (2 * 96 * 97 * 4)

// -------------------- scratch (device globals; no allocs) --------------------
__device__ float  g_Nu[NJ * RES];      // B-spline basis, p=2, [i][u]
__device__ float  g_sv[RES];           // sum over i of Nv[i][v]
__device__ float  g_X[NROWS * DIMX];   // curve matrix: pred rows 0..2047, label 2048..4095
__device__ float  g_cov[DIMX * DIMX];  // Xc^T Xc (un-normalized)
__device__ double g_sumP[DIMX];
__device__ double g_sumL[DIMX];
__device__ unsigned long long g_inter;

// -------------------- K0: zero accumulators --------------------
__global__ void k_zero() {
    int t = threadIdx.x;
    for (int i = t; i < DIMX * DIMX; i += blockDim.x) g_cov[i] = 0.0f;
    if (t < DIMX) { g_sumP[t] = 0.0; g_sumL[t] = 0.0; }
    if (t == 0) g_inter = 0ull;
}

// -------------------- K1: basis matrices (replicates reference recurrence) ---
__global__ void k_basis() {
    int uj = threadIdx.x;
    if (uj >= RES) return;
    float u = (float)((double)uj / 31.0);

    // ---- Nu: n=68, p=2, L=71, internal knots (i-2)/66 ----
    {
        const int L = NJ + 2 + 1;  // 71
        float kn[71];
        for (int i = 0; i < L; i++) {
            if (i < 3)            kn[i] = 0.0f;
            else if (i >= L - 3)  kn[i] = 1.0f;
            else                  kn[i] = (float)((double)(i - 2) / 66.0);
        }
        float N[70];
        for (int i = 0; i < L - 1; i++)
            N[i] = (kn[i] <= u && u < kn[i + 1]) ? 1.0f : 0.0f;
        for (int d = 1; d <= 2; d++) {
            int m = (L - 1) - d;
            for (int i = 0; i < m; i++) {
                float ld = kn[i + d] - kn[i];
                float rd = kn[i + d + 1] - kn[i + 1];
                float t1 = (ld == 0.0f) ? 0.0f : (u - kn[i]) / ld * N[i];
                float t2 = (rd == 0.0f) ? 0.0f : (kn[i + d + 1] - u) / rd * N[i + 1];
                N[i] = t1 + t2;   // in-place safe: N[i+1] still old
            }
        }
        for (int i = 0; i < NJ; i++) g_Nu[i * RES + uj] = N[i];
    }

    // ---- Nv: n=68, q=3, L=72, internal knots (i-3)/65; only sv needed ----
    {
        const int L = NJ + 3 + 1;  // 72
        float kn[72];
        for (int i = 0; i < L; i++) {
            if (i < 4)            kn[i] = 0.0f;
            else if (i >= L - 4)  kn[i] = 1.0f;
            else                  kn[i] = (float)((double)(i - 3) / 65.0);
        }
        float N[71];
        for (int i = 0; i < L - 1; i++)
            N[i] = (kn[i] <= u && u < kn[i + 1]) ? 1.0f : 0.0f;
        for (int d = 1; d <= 3; d++) {
            int m = (L - 1) - d;
            for (int i = 0; i < m; i++) {
                float ld = kn[i + d] - kn[i];
                float rd = kn[i + d + 1] - kn[i + 1];
                float t1 = (ld == 0.0f) ? 0.0f : (u - kn[i]) / ld * N[i];
                float t2 = (rd == 0.0f) ? 0.0f : (kn[i + d + 1] - u) / rd * N[i + 1];
                N[i] = t1 + t2;
            }
        }
        float s = 0.0f;
        for (int i = 0; i < NJ; i++) s += N[i];
        g_sv[uj] = s;
    }
}

// -------------------- K2: curves + IoU count -------------------------------
__global__ void k_curves(const float* __restrict__ pred,
                         const float* __restrict__ label) {
    __shared__ float sNu[NJ * RES];
    __shared__ float sP[NJ * 3], sL[NJ * 3];
    __shared__ float cP[DIMX], cL[DIMX];

    int b = blockIdx.x;
    int t = threadIdx.x;  // 96 threads

    for (int i = t; i < NJ * RES; i += 96) sNu[i] = g_Nu[i];
    for (int i = t; i < NJ * 3; i += 96) {
        sP[i] = pred[b * (NJ * 3) + i];
        sL[i] = label[b * (NJ * 3) + i];
    }
    __syncthreads();

    int u = t / 3, c = t - u * 3;
    float aP = 0.0f, aL = 0.0f;
#pragma unroll 4
    for (int i = 0; i < NJ; i++) {
        float w = sNu[i * RES + u];
        aP += sP[i * 3 + c] * w;
        aL += sL[i * 3 + c] * w;
    }
    g_X[b * DIMX + t]        = aP;
    g_X[(NB + b) * DIMX + t] = aL;
    cP[t] = aP; cL[t] = aL;
    __syncthreads();

    if (t < 32) {
        float p0 = cP[t * 3], p1 = cP[t * 3 + 1], p2 = cP[t * 3 + 2];
        float l0 = cL[t * 3], l1 = cL[t * 3 + 1], l2 = cL[t * 3 + 2];
        int cnt = 0;
#pragma unroll
        for (int v = 0; v < RES; v++) {
            float sv = g_sv[v];
            float d0 = p0 * sv - l0 * sv;
            float d1 = p1 * sv - l1 * sv;
            float d2 = p2 * sv - l2 * sv;
            float s = (d0 * d0 + d1 * d1) + d2 * d2;
            cnt += (s < 0.25f) ? 1 : 0;
        }
#pragma unroll
        for (int o = 16; o > 0; o >>= 1)
            cnt += __shfl_down_sync(0xffffffffu, cnt, o);
        if (t == 0) atomicAdd(&g_inter, (unsigned long long)cnt);
    }
}

// -------------------- K3: column means (double accum) ----------------------
__global__ void k_means() {
    int blk = blockIdx.x;   // 32 blocks x 128 rows
    int t = threadIdx.x;    // 96
    int row0 = blk * 128;
    float acc = 0.0f;
    for (int i = 0; i < 128; i++)
        acc += g_X[(row0 + i) * DIMX + t];
    if (blk < 16) atomicAdd(&g_sumP[t], (double)acc);
    else          atomicAdd(&g_sumL[t], (double)acc);
}

// -------------------- K4: 96x96 covariance (chunked fp32) ------------------
__global__ void k_cov() {
    __shared__ float mu[DIMX];
    int r = blockIdx.x;      // 0..95
    int ch = blockIdx.y;     // 0..15
    int t = threadIdx.x;     // 96
    if (t < DIMX) mu[t] = (float)((g_sumP[t] + g_sumL[t]) / 4096.0);
    __syncthreads();

    int row0 = ch * 256;
    float mur = mu[r];
    float muk = mu[t];
    float acc = 0.0f;
#pragma unroll 4
    for (int i = 0; i < 256; i++) {
        int row = row0 + i;
        float xr = g_X[row * DIMX + r] - mur;
        float xk = g_X[row * DIMX + t] - muk;
        acc += xr * xk;
    }
    atomicAdd(&g_cov[r * DIMX + t], acc);
}

// -------------------- K5: parallel Jacobi eig + finalize -------------------
__global__ void k_jacobi(float* __restrict__ out) {
    extern __shared__ float sm[];
    float* A = sm;                 // 96 x 97 (padded)
    float* V = sm + 96 * 97;       // 96 x 97
    __shared__ float rc[48], rs[48];
    __shared__ int   rp[48], rq[48];
    __shared__ float sd[DIMX];

    int t = threadIdx.x;
    const int NT = blockDim.x;

    for (int idx = t; idx < 96 * 96; idx += NT) {
        int i = idx / 96, j = idx - i * 96;
        A[i * 97 + j] = g_cov[idx] * (1.0f / 4095.0f);
        V[i * 97 + j] = (i == j) ? 1.0f : 0.0f;
    }
    __syncthreads();

    for (int sweep = 0; sweep < NSWEEPS; sweep++) {
        for (int r = 0; r < 95; r++) {
            // rotation angles for 48 disjoint pairs (tournament schedule)
            if (t < 48) {
                int p, q;
                if (t == 0) { p = 95; q = r; }
                else { p = (r + t) % 95; q = (r + 95 - t) % 95; }
                rp[t] = p; rq[t] = q;
                float app = A[p * 97 + p];
                float aqq = A[q * 97 + q];
                float apq = A[p * 97 + q];
                float c = 1.0f, s = 0.0f;
                if (fabsf(apq) > 1e-30f) {
                    float tau = (aqq - app) / (2.0f * apq);
                    float tt = (tau >= 0.0f)
                                   ? 1.0f / (tau + sqrtf(1.0f + tau * tau))
                                   : 1.0f / (tau - sqrtf(1.0f + tau * tau));
                    c = rsqrtf(1.0f + tt * tt);
                    s = tt * c;
                }
                rc[t] = c; rs[t] = s;
            }
            __syncthreads();
            // row phase: A <- J^T A
            for (int idx = t; idx < 48 * 96; idx += NT) {
                int k = idx / 96, j = idx - k * 96;
                int p = rp[k], q = rq[k];
                float c = rc[k], s = rs[k];
                float ap = A[p * 97 + j], aq = A[q * 97 + j];
                A[p * 97 + j] = c * ap - s * aq;
                A[q * 97 + j] = s * ap + c * aq;
            }
            __syncthreads();
            // col phase: A <- A J ; V <- V J
            for (int idx = t; idx < 2 * 48 * 96; idx += NT) {
                int half = idx / (48 * 96);
                int rem = idx - half * (48 * 96);
                int k = rem / 96, j = rem - k * 96;
                int p = rp[k], q = rq[k];
                float c = rc[k], s = rs[k];
                if (half == 0) {
                    float ap = A[j * 97 + p], aq = A[j * 97 + q];
                    A[j * 97 + p] = c * ap - s * aq;
                    A[j * 97 + q] = s * ap + c * aq;
                } else {
                    float vp = V[j * 97 + p], vq = V[j * 97 + q];
                    V[j * 97 + p] = c * vp - s * vq;
                    V[j * 97 + q] = s * vp + c * vq;
                }
            }
            __syncthreads();
        }
    }

    if (t < DIMX)
        sd[t] = (float)(g_sumP[t] / 2048.0 - g_sumL[t] / 2048.0);
    __syncthreads();

    if (t == 0) {
        // top-3 eigenvalues on the diagonal
        int i0 = 0, i1 = -1, i2 = -1;
        float v0 = -1e30f, v1 = -1e30f, v2 = -1e30f;
        for (int i = 0; i < 96; i++) {
            float e = A[i * 97 + i];
            if (e > v0)      { v2 = v1; i2 = i1; v1 = v0; i1 = i0; v0 = e; i0 = i; }
            else if (e > v1) { v2 = v1; i2 = i1; v1 = e;  i1 = i; }
            else if (e > v2) { v2 = e;  i2 = i; }
        }
        int idxs[3] = { i0, i1, i2 };
        float ssum = 0.0f;
        for (int k = 0; k < 3; k++) {
            float pr = 0.0f;
            for (int j = 0; j < 96; j++) pr += sd[j] * V[j * 97 + idxs[k]];
            ssum += pr * pr;
        }
        float sv2 = 0.0f;
        for (int v = 0; v < RES; v++) sv2 += g_sv[v] * g_sv[v];
        float dist_pca = sqrtf(sv2) * sqrtf(ssum);
        float pca_loss = 1.0f - dist_pca;

        float inter = (float)g_inter;
        float uni = 2048.0f - inter;   // reference: P + P - inter (P = 1024)
        float iou_loss = 1.0f - inter / uni;

        out[0] = pca_loss + iou_loss;
    }
}

// -------------------- launcher --------------------
extern "C" void kernel_launch(void* const* d_in, const int* in_sizes, int n_in,
                              void* d_out, int out_size) {
    const float* pred  = (const float*)d_in[0];
    const float* label = (const float*)d_in[1];
    // d_in[2] = target_weight (unused by the reference math)
    float* out = (float*)d_out;

    cudaFuncSetAttribute(k_jacobi, cudaFuncAttributeMaxDynamicSharedMemorySize,
                         JAC_SMEM);

    k_zero<<<1, 256>>>();
    k_basis<<<1, 32>>>();
    k_curves<<<NB, 96>>>(pred, label);
    k_means<<<32, 96>>>();
    k_cov<<<dim3(96, 16), 96>>>();
    k_jacobi<<<1, JAC_THREADS, JAC_SMEM>>>(out);
}

// round 4
// speedup vs baseline: 3.4542x; 3.4542x over previous
#include <cuda_runtime.h>
#include <math.h>

#define NJ   68
#define RES  32
#define NB   2048
#define NROWS 4096
#define DIMX 96
#define MAX_SWEEPS 10
#define JAC_THREADS 1024

// -------------------- scratch (device globals; no allocs) --------------------
__device__ float  g_Nu[NJ * RES];      // B-spline basis, p=2, [i][u]
__device__ float  g_sv[RES];           // sum over i of Nv[i][v]
__device__ float  g_X[NROWS * DIMX];   // curves: pred rows 0..2047, label 2048..4095
__device__ float  g_cov[DIMX * DIMX];  // Xc^T Xc (un-normalized)
__device__ double g_sumP[DIMX];
__device__ double g_sumL[DIMX];
__device__ unsigned long long g_inter;

// -------------------- K0: zero accumulators --------------------
__global__ void k_zero() {
    int t = threadIdx.x;
    for (int i = t; i < DIMX * DIMX; i += blockDim.x) g_cov[i] = 0.0f;
    if (t < DIMX) { g_sumP[t] = 0.0; g_sumL[t] = 0.0; }
    if (t == 0) g_inter = 0ull;
}

// -------------------- K1: basis matrices (replicates reference recurrence) ---
__global__ void k_basis() {
    int uj = threadIdx.x;
    if (uj >= RES) return;
    float u = (float)((double)uj / 31.0);

    // ---- Nu: n=68, p=2, L=71, internal knots (i-2)/66 ----
    {
        const int L = NJ + 2 + 1;  // 71
        float kn[71];
        for (int i = 0; i < L; i++) {
            if (i < 3)            kn[i] = 0.0f;
            else if (i >= L - 3)  kn[i] = 1.0f;
            else                  kn[i] = (float)((double)(i - 2) / 66.0);
        }
        float N[70];
        for (int i = 0; i < L - 1; i++)
            N[i] = (kn[i] <= u && u < kn[i + 1]) ? 1.0f : 0.0f;
        for (int d = 1; d <= 2; d++) {
            int m = (L - 1) - d;
            for (int i = 0; i < m; i++) {
                float ld = kn[i + d] - kn[i];
                float rd = kn[i + d + 1] - kn[i + 1];
                float t1 = (ld == 0.0f) ? 0.0f : (u - kn[i]) / ld * N[i];
                float t2 = (rd == 0.0f) ? 0.0f : (kn[i + d + 1] - u) / rd * N[i + 1];
                N[i] = t1 + t2;
            }
        }
        for (int i = 0; i < NJ; i++) g_Nu[i * RES + uj] = N[i];
    }

    // ---- Nv: n=68, q=3, L=72, internal knots (i-3)/65; only sv needed ----
    {
        const int L = NJ + 3 + 1;  // 72
        float kn[72];
        for (int i = 0; i < L; i++) {
            if (i < 4)            kn[i] = 0.0f;
            else if (i >= L - 4)  kn[i] = 1.0f;
            else                  kn[i] = (float)((double)(i - 3) / 65.0);
        }
        float N[71];
        for (int i = 0; i < L - 1; i++)
            N[i] = (kn[i] <= u && u < kn[i + 1]) ? 1.0f : 0.0f;
        for (int d = 1; d <= 3; d++) {
            int m = (L - 1) - d;
            for (int i = 0; i < m; i++) {
                float ld = kn[i + d] - kn[i];
                float rd = kn[i + d + 1] - kn[i + 1];
                float t1 = (ld == 0.0f) ? 0.0f : (u - kn[i]) / ld * N[i];
                float t2 = (rd == 0.0f) ? 0.0f : (kn[i + d + 1] - u) / rd * N[i + 1];
                N[i] = t1 + t2;
            }
        }
        float s = 0.0f;
        for (int i = 0; i < NJ; i++) s += N[i];
        g_sv[uj] = s;
    }
}

// -------------------- K2: curves + IoU count -------------------------------
__global__ void k_curves(const float* __restrict__ pred,
                         const float* __restrict__ label) {
    __shared__ float sNu[NJ * RES];
    __shared__ float sP[NJ * 3], sL[NJ * 3];
    __shared__ float cP[DIMX], cL[DIMX];

    int b = blockIdx.x;
    int t = threadIdx.x;  // 96 threads

    for (int i = t; i < NJ * RES; i += 96) sNu[i] = g_Nu[i];
    for (int i = t; i < NJ * 3; i += 96) {
        sP[i] = pred[b * (NJ * 3) + i];
        sL[i] = label[b * (NJ * 3) + i];
    }
    __syncthreads();

    int u = t / 3, c = t - u * 3;
    float aP = 0.0f, aL = 0.0f;
#pragma unroll 4
    for (int i = 0; i < NJ; i++) {
        float w = sNu[i * RES + u];
        aP += sP[i * 3 + c] * w;
        aL += sL[i * 3 + c] * w;
    }
    g_X[b * DIMX + t]        = aP;
    g_X[(NB + b) * DIMX + t] = aL;
    cP[t] = aP; cL[t] = aL;
    __syncthreads();

    if (t < 32) {
        float p0 = cP[t * 3], p1 = cP[t * 3 + 1], p2 = cP[t * 3 + 2];
        float l0 = cL[t * 3], l1 = cL[t * 3 + 1], l2 = cL[t * 3 + 2];
        int cnt = 0;
#pragma unroll
        for (int v = 0; v < RES; v++) {
            float sv = g_sv[v];
            float d0 = p0 * sv - l0 * sv;
            float d1 = p1 * sv - l1 * sv;
            float d2 = p2 * sv - l2 * sv;
            float s = (d0 * d0 + d1 * d1) + d2 * d2;
            cnt += (s < 0.25f) ? 1 : 0;
        }
#pragma unroll
        for (int o = 16; o > 0; o >>= 1)
            cnt += __shfl_down_sync(0xffffffffu, cnt, o);
        if (t == 0) atomicAdd(&g_inter, (unsigned long long)cnt);
    }
}

// -------------------- K3: column means (double accum) ----------------------
__global__ void k_means() {
    int blk = blockIdx.x;   // 32 blocks x 128 rows
    int t = threadIdx.x;    // 96
    int row0 = blk * 128;
    float acc = 0.0f;
    for (int i = 0; i < 128; i++)
        acc += g_X[(row0 + i) * DIMX + t];
    if (blk < 16) atomicAdd(&g_sumP[t], (double)acc);
    else          atomicAdd(&g_sumL[t], (double)acc);
}

// -------------------- K4: 96x96 covariance (chunked fp32) ------------------
__global__ void k_cov() {
    __shared__ float mu[DIMX];
    int r = blockIdx.x;      // 0..95
    int ch = blockIdx.y;     // 0..15
    int t = threadIdx.x;     // 96
    if (t < DIMX) mu[t] = (float)((g_sumP[t] + g_sumL[t]) / 4096.0);
    __syncthreads();

    int row0 = ch * 256;
    float mur = mu[r];
    float muk = mu[t];
    float acc = 0.0f;
#pragma unroll 4
    for (int i = 0; i < 256; i++) {
        int row = row0 + i;
        float xr = g_X[row * DIMX + r] - mur;
        float xk = g_X[row * DIMX + t] - muk;
        acc += xr * xk;
    }
    atomicAdd(&g_cov[r * DIMX + t], acc);
}

// -------------------- K5: block-fused parallel Jacobi + finalize -----------
// Two-sided Jacobi where each round's update is decomposed into 48x48
// independent 2x2 block rotations  B_ab <- L_a * B_ab * M_b  (in-place,
// no cross-block deps). Eigenvector matrix is never formed; we track
// w = V^T d instead (2 elements per rotation).
__global__ void __launch_bounds__(JAC_THREADS)
k_jacobi(float* __restrict__ out) {
    __shared__ float A[96 * 97];         // padded rows
    __shared__ float rc[48], rs[48];
    __shared__ int   rp[48], rq[48];
    __shared__ float w[DIMX];
    __shared__ float s_fro;
    __shared__ float s_off;

    const int t = threadIdx.x;

    if (t == 0) { s_fro = 0.0f; }
    if (t < DIMX)
        w[t] = (float)(g_sumP[t] / 2048.0 - g_sumL[t] / 2048.0);
    __syncthreads();

    // load A (normalized cov) + Frobenius norm^2 (rotation-invariant)
    float fro_loc = 0.0f;
    for (int idx = t; idx < 96 * 96; idx += JAC_THREADS) {
        int i = idx / 96, j = idx - i * 96;
        float v = g_cov[idx] * (1.0f / 4095.0f);
        A[i * 97 + j] = v;
        fro_loc += v * v;
    }
#pragma unroll
    for (int o = 16; o > 0; o >>= 1)
        fro_loc += __shfl_down_sync(0xffffffffu, fro_loc, o);
    if ((t & 31) == 0) atomicAdd(&s_fro, fro_loc);
    __syncthreads();
    const float tol = 1e-12f * s_fro;

    for (int sweep = 0; sweep < MAX_SWEEPS; sweep++) {
        for (int r = 0; r < 95; r++) {
            // --- rotation angles for 48 disjoint pairs + w update ---
            if (t < 48) {
                int p, q;
                if (t == 0) { p = 95; q = r; }
                else { p = (r + t) % 95; q = (r + 95 - t) % 95; }
                rp[t] = p; rq[t] = q;
                float app = A[p * 97 + p];
                float aqq = A[q * 97 + q];
                float apq = A[p * 97 + q];
                float c = 1.0f, s = 0.0f;
                if (fabsf(apq) > 1e-30f) {
                    float tau = (aqq - app) / (2.0f * apq);
                    float tt = (tau >= 0.0f)
                                   ? 1.0f / (tau + sqrtf(1.0f + tau * tau))
                                   : 1.0f / (tau - sqrtf(1.0f + tau * tau));
                    c = rsqrtf(1.0f + tt * tt);
                    s = tt * c;
                }
                rc[t] = c; rs[t] = s;
                // w <- J^T w  (same formula as a column update of V)
                float wp = w[p], wq = w[q];
                w[p] = c * wp - s * wq;
                w[q] = s * wp + c * wq;
            }
            __syncthreads();

            // --- 2304 independent 2x2 block rotations, in place ---
            for (int e = t; e < 48 * 48; e += JAC_THREADS) {
                int a = e / 48, b = e - a * 48;
                int pa = rp[a], qa = rq[a];
                int pb = rp[b], qb = rq[b];
                float ca = rc[a], sa = rs[a];
                float cb = rc[b], sb = rs[b];
                float x00 = A[pa * 97 + pb], x01 = A[pa * 97 + qb];
                float x10 = A[qa * 97 + pb], x11 = A[qa * 97 + qb];
                // left: rows (p,q) <- (c*p - s*q, s*p + c*q)
                float y00 = ca * x00 - sa * x10;
                float y01 = ca * x01 - sa * x11;
                float y10 = sa * x00 + ca * x10;
                float y11 = sa * x01 + ca * x11;
                // right: cols (p,q) <- (c*p - s*q, s*p + c*q)
                A[pa * 97 + pb] = cb * y00 - sb * y01;
                A[pa * 97 + qb] = sb * y00 + cb * y01;
                A[qa * 97 + pb] = cb * y10 - sb * y11;
                A[qa * 97 + qb] = sb * y10 + cb * y11;
            }
            __syncthreads();
        }

        // --- convergence check (once per sweep) ---
        if (t == 0) s_off = 0.0f;
        __syncthreads();
        float off_loc = 0.0f;
        for (int idx = t; idx < 96 * 96; idx += JAC_THREADS) {
            int i = idx / 96, j = idx - i * 96;
            if (i != j) { float v = A[i * 97 + j]; off_loc += v * v; }
        }
#pragma unroll
        for (int o = 16; o > 0; o >>= 1)
            off_loc += __shfl_down_sync(0xffffffffu, off_loc, o);
        if ((t & 31) == 0) atomicAdd(&s_off, off_loc);
        __syncthreads();
        if (s_off <= tol) break;
    }

    if (t == 0) {
        // top-3 eigenvalues on the diagonal
        int i0 = 0, i1 = -1, i2 = -1;
        float v0 = -1e30f, v1 = -1e30f, v2 = -1e30f;
        for (int i = 0; i < 96; i++) {
            float e = A[i * 97 + i];
            if (e > v0)      { v2 = v1; i2 = i1; v1 = v0; i1 = i0; v0 = e; i0 = i; }
            else if (e > v1) { v2 = v1; i2 = i1; v1 = e;  i1 = i; }
            else if (e > v2) { v2 = e;  i2 = i; }
        }
        float ssum = w[i0] * w[i0] + w[i1] * w[i1] + w[i2] * w[i2];
        float sv2 = 0.0f;
        for (int v = 0; v < RES; v++) sv2 += g_sv[v] * g_sv[v];
        float dist_pca = sqrtf(sv2) * sqrtf(ssum);
        float pca_loss = 1.0f - dist_pca;

        float inter = (float)g_inter;
        float uni = 2048.0f - inter;   // reference: P + P - inter
        float iou_loss = 1.0f - inter / uni;

        out[0] = pca_loss + iou_loss;
    }
}

// -------------------- launcher --------------------
extern "C" void kernel_launch(void* const* d_in, const int* in_sizes, int n_in,
                              void* d_out, int out_size) {
    const float* pred  = (const float*)d_in[0];
    const float* label = (const float*)d_in[1];
    float* out = (float*)d_out;

    k_zero<<<1, 256>>>();
    k_basis<<<1, 32>>>();
    k_curves<<<NB, 96>>>(pred, label);
    k_means<<<32, 96>>>();
    k_cov<<<dim3(96, 16), 96>>>();
    k_jacobi<<<1, JAC_THREADS>>>(out);
}

// round 6
// speedup vs baseline: 11.2399x; 3.2540x over previous
#include <cuda_runtime.h>
#include <math.h>

#define NJ   68
#define RES  32
#define NB   2048
#define NROWS 4096
#define DIMX 96
#define BVEC 8          // power-iteration block size
#define KITER 48        // power iterations (ratio <=0.82 -> 0.82^48 ~ 7e-5)

// -------------------- scratch (device globals; no allocs) --------------------
__device__ float  g_Nu[NJ * RES];
__device__ float  g_sv[RES];
__device__ float  g_X[NROWS * DIMX];
__device__ float  g_cov[DIMX * DIMX];
__device__ double g_sumP[DIMX];
__device__ double g_sumL[DIMX];
__device__ unsigned long long g_inter;

// -------------------- K0: zero accumulators --------------------
__global__ void k_zero() {
    int t = threadIdx.x;
    for (int i = t; i < DIMX * DIMX; i += blockDim.x) g_cov[i] = 0.0f;
    if (t < DIMX) { g_sumP[t] = 0.0; g_sumL[t] = 0.0; }
    if (t == 0) g_inter = 0ull;
}

// -------------------- K1: basis matrices (replicates reference recurrence) ---
__global__ void k_basis() {
    int uj = threadIdx.x;
    if (uj >= RES) return;
    float u = (float)((double)uj / 31.0);
    {
        const int L = NJ + 2 + 1;  // 71
        float kn[71];
        for (int i = 0; i < L; i++) {
            if (i < 3)            kn[i] = 0.0f;
            else if (i >= L - 3)  kn[i] = 1.0f;
            else                  kn[i] = (float)((double)(i - 2) / 66.0);
        }
        float N[70];
        for (int i = 0; i < L - 1; i++)
            N[i] = (kn[i] <= u && u < kn[i + 1]) ? 1.0f : 0.0f;
        for (int d = 1; d <= 2; d++) {
            int m = (L - 1) - d;
            for (int i = 0; i < m; i++) {
                float ld = kn[i + d] - kn[i];
                float rd = kn[i + d + 1] - kn[i + 1];
                float t1 = (ld == 0.0f) ? 0.0f : (u - kn[i]) / ld * N[i];
                float t2 = (rd == 0.0f) ? 0.0f : (kn[i + d + 1] - u) / rd * N[i + 1];
                N[i] = t1 + t2;
            }
        }
        for (int i = 0; i < NJ; i++) g_Nu[i * RES + uj] = N[i];
    }
    {
        const int L = NJ + 3 + 1;  // 72
        float kn[72];
        for (int i = 0; i < L; i++) {
            if (i < 4)            kn[i] = 0.0f;
            else if (i >= L - 4)  kn[i] = 1.0f;
            else                  kn[i] = (float)((double)(i - 3) / 65.0);
        }
        float N[71];
        for (int i = 0; i < L - 1; i++)
            N[i] = (kn[i] <= u && u < kn[i + 1]) ? 1.0f : 0.0f;
        for (int d = 1; d <= 3; d++) {
            int m = (L - 1) - d;
            for (int i = 0; i < m; i++) {
                float ld = kn[i + d] - kn[i];
                float rd = kn[i + d + 1] - kn[i + 1];
                float t1 = (ld == 0.0f) ? 0.0f : (u - kn[i]) / ld * N[i];
                float t2 = (rd == 0.0f) ? 0.0f : (kn[i + d + 1] - u) / rd * N[i + 1];
                N[i] = t1 + t2;
            }
        }
        float s = 0.0f;
        for (int i = 0; i < NJ; i++) s += N[i];
        g_sv[uj] = s;
    }
}

// -------------------- K2: curves + IoU count -------------------------------
__global__ void k_curves(const float* __restrict__ pred,
                         const float* __restrict__ label) {
    __shared__ float sNu[NJ * RES];
    __shared__ float sP[NJ * 3], sL[NJ * 3];
    __shared__ float cP[DIMX], cL[DIMX];

    int b = blockIdx.x;
    int t = threadIdx.x;  // 96

    for (int i = t; i < NJ * RES; i += 96) sNu[i] = g_Nu[i];
    for (int i = t; i < NJ * 3; i += 96) {
        sP[i] = pred[b * (NJ * 3) + i];
        sL[i] = label[b * (NJ * 3) + i];
    }
    __syncthreads();

    int u = t / 3, c = t - u * 3;
    float aP = 0.0f, aL = 0.0f;
#pragma unroll 4
    for (int i = 0; i < NJ; i++) {
        float w = sNu[i * RES + u];
        aP += sP[i * 3 + c] * w;
        aL += sL[i * 3 + c] * w;
    }
    g_X[b * DIMX + t]        = aP;
    g_X[(NB + b) * DIMX + t] = aL;
    cP[t] = aP; cL[t] = aL;
    __syncthreads();

    if (t < 32) {
        float p0 = cP[t * 3], p1 = cP[t * 3 + 1], p2 = cP[t * 3 + 2];
        float l0 = cL[t * 3], l1 = cL[t * 3 + 1], l2 = cL[t * 3 + 2];
        int cnt = 0;
#pragma unroll
        for (int v = 0; v < RES; v++) {
            float sv = g_sv[v];
            float d0 = p0 * sv - l0 * sv;
            float d1 = p1 * sv - l1 * sv;
            float d2 = p2 * sv - l2 * sv;
            float s = (d0 * d0 + d1 * d1) + d2 * d2;
            cnt += (s < 0.25f) ? 1 : 0;
        }
#pragma unroll
        for (int o = 16; o > 0; o >>= 1)
            cnt += __shfl_down_sync(0xffffffffu, cnt, o);
        if (t == 0) atomicAdd(&g_inter, (unsigned long long)cnt);
    }
}

// -------------------- K3: column means (double accum) ----------------------
__global__ void k_means() {
    int blk = blockIdx.x;   // 128 blocks x 32 rows
    int t = threadIdx.x;    // 96
    int row0 = blk * 32;
    float acc = 0.0f;
    for (int i = 0; i < 32; i++)
        acc += g_X[(row0 + i) * DIMX + t];
    if (blk < 64) atomicAdd(&g_sumP[t], (double)acc);
    else          atomicAdd(&g_sumL[t], (double)acc);
}

// -------------------- K4: covariance, 8 cov-rows per block -----------------
__global__ void k_cov() {
    __shared__ float mu[DIMX];
    int rb = blockIdx.x * 8;   // cov row base (grid.x = 12)
    int ch = blockIdx.y;       // chunk (grid.y = 16)
    int t = threadIdx.x;       // 96
    if (t < DIMX) mu[t] = (float)((g_sumP[t] + g_sumL[t]) / 4096.0);
    __syncthreads();

    float mur[8];
#pragma unroll
    for (int s = 0; s < 8; s++) mur[s] = mu[rb + s];
    float muk = mu[t];

    float acc[8] = {0, 0, 0, 0, 0, 0, 0, 0};
    int row0 = ch * 256;
    for (int i = 0; i < 256; i++) {
        const float* xrow = &g_X[(row0 + i) * DIMX];
        float xk = xrow[t] - muk;
#pragma unroll
        for (int s = 0; s < 8; s++)
            acc[s] += (xrow[rb + s] - mur[s]) * xk;
    }
#pragma unroll
    for (int s = 0; s < 8; s++)
        atomicAdd(&g_cov[(rb + s) * DIMX + t], acc[s]);
}

// -------------------- K5: block power iteration + Rayleigh-Ritz ------------
// Top-3 eigenspace of the 96x96 covariance. Spectrum has top triple ~1.0
// (exact decoupled G-eigenvalue from N_i(0)=delta_i0) vs lambda4 <= ~0.78
// (Gershgorin on the B-spline Gram), so ratio <= 0.82 and K=48 converges the
// 3-subspace to ~1e-4 angle; Rayleigh-Ritz resolves the near-degenerate top
// triple exactly (only the 3-subspace matters for ssum).
__global__ void __launch_bounds__(96)
k_eig(float* __restrict__ out) {
    __shared__ float C[96 * 97];
    __shared__ float Ysh[96 * 8];
    __shared__ float Zsh[96 * 8];
    __shared__ float S8[64], R8[64], Rinv[8];
    __shared__ float W8[64];
    __shared__ float T8[8 * 9], V8[8 * 9];
    __shared__ float rc4[4], rs4[4];
    __shared__ int   rp4[4], rq4[4];
    __shared__ float dvec[DIMX], gvec[8];

    const int t = threadIdx.x;  // 96 threads

    for (int idx = t; idx < 96 * 96; idx += 96) {
        int i = idx / 96, j = idx - i * 96;
        C[i * 97 + j] = g_cov[idx] * (1.0f / 4095.0f);
    }
    dvec[t] = (float)(g_sumP[t] / 2048.0 - g_sumL[t] / 2048.0);
#pragma unroll
    for (int s = 0; s < 8; s++)
        Ysh[t * 8 + s] = cosf(0.7f * (float)((t + 1) * (s + 1))) +
                         ((t == s) ? 0.05f : 0.0f);
    __syncthreads();

    for (int it = 0; it < KITER; it++) {
        // Z = C * Y
        {
            float a0=0,a1=0,a2=0,a3=0,a4=0,a5=0,a6=0,a7=0;
#pragma unroll 4
            for (int j = 0; j < 96; j++) {
                float c = C[t * 97 + j];
                float4 y0 = *(const float4*)&Ysh[j * 8];
                float4 y1 = *(const float4*)&Ysh[j * 8 + 4];
                a0 += c * y0.x; a1 += c * y0.y; a2 += c * y0.z; a3 += c * y0.w;
                a4 += c * y1.x; a5 += c * y1.y; a6 += c * y1.z; a7 += c * y1.w;
            }
            float4* zp = (float4*)&Zsh[t * 8];
            zp[0] = make_float4(a0, a1, a2, a3);
            zp[1] = make_float4(a4, a5, a6, a7);
        }
        __syncthreads();

        if (it % 3 == 0) {
            // CholQR: Y = Z * R^-1 with R'R = Z'Z
            if (t < 64) {
                int a = t >> 3, b = t & 7;
                float s = 0.0f;
                for (int i = 0; i < 96; i++)
                    s += Zsh[i * 8 + a] * Zsh[i * 8 + b];
                S8[a * 8 + b] = s;
            }
            __syncthreads();
            if (t == 0) {
#pragma unroll
                for (int k = 0; k < 8; k++) {
                    float dk = sqrtf(fmaxf(S8[k * 8 + k], 1e-30f));
                    float inv = 1.0f / dk;
                    R8[k * 8 + k] = dk; Rinv[k] = inv;
                    for (int j = k + 1; j < 8; j++)
                        R8[k * 8 + j] = S8[k * 8 + j] * inv;
                    for (int i = k + 1; i < 8; i++)
                        for (int j = i; j < 8; j++)
                            S8[i * 8 + j] -= R8[k * 8 + i] * R8[k * 8 + j];
                }
            }
            __syncthreads();
            {
                float z[8], y[8];
#pragma unroll
                for (int s = 0; s < 8; s++) z[s] = Zsh[t * 8 + s];
#pragma unroll
                for (int s = 0; s < 8; s++) {
                    float v = z[s];
                    for (int k = 0; k < s; k++) v -= y[k] * R8[k * 8 + s];
                    y[s] = v * Rinv[s];
                }
#pragma unroll
                for (int s = 0; s < 8; s++) Ysh[t * 8 + s] = y[s];
            }
        } else {
            float4* yp = (float4*)&Ysh[t * 8];
            const float4* zp = (const float4*)&Zsh[t * 8];
            yp[0] = zp[0]; yp[1] = zp[1];
        }
        __syncthreads();
    }

    // final orthonormalization of Y (in place: S from Y, then row-solve)
    if (t < 64) {
        int a = t >> 3, b = t & 7;
        float s = 0.0f;
        for (int i = 0; i < 96; i++)
            s += Ysh[i * 8 + a] * Ysh[i * 8 + b];
        S8[a * 8 + b] = s;
    }
    __syncthreads();
    if (t == 0) {
#pragma unroll
        for (int k = 0; k < 8; k++) {
            float dk = sqrtf(fmaxf(S8[k * 8 + k], 1e-30f));
            float inv = 1.0f / dk;
            R8[k * 8 + k] = dk; Rinv[k] = inv;
            for (int j = k + 1; j < 8; j++)
                R8[k * 8 + j] = S8[k * 8 + j] * inv;
            for (int i = k + 1; i < 8; i++)
                for (int j = i; j < 8; j++)
                    S8[i * 8 + j] -= R8[k * 8 + i] * R8[k * 8 + j];
        }
    }
    __syncthreads();
    {
        float z[8], y[8];
#pragma unroll
        for (int s = 0; s < 8; s++) z[s] = Ysh[t * 8 + s];
#pragma unroll
        for (int s = 0; s < 8; s++) {
            float v = z[s];
            for (int k = 0; k < s; k++) v -= y[k] * R8[k * 8 + s];
            y[s] = v * Rinv[s];
        }
#pragma unroll
        for (int s = 0; s < 8; s++) Ysh[t * 8 + s] = y[s];
    }
    __syncthreads();

    // Z = C*Y once more for Rayleigh-Ritz T = Y' C Y
    {
        float a0=0,a1=0,a2=0,a3=0,a4=0,a5=0,a6=0,a7=0;
#pragma unroll 4
        for (int j = 0; j < 96; j++) {
            float c = C[t * 97 + j];
            float4 y0 = *(const float4*)&Ysh[j * 8];
            float4 y1 = *(const float4*)&Ysh[j * 8 + 4];
            a0 += c * y0.x; a1 += c * y0.y; a2 += c * y0.z; a3 += c * y0.w;
            a4 += c * y1.x; a5 += c * y1.y; a6 += c * y1.z; a7 += c * y1.w;
        }
        float4* zp = (float4*)&Zsh[t * 8];
        zp[0] = make_float4(a0, a1, a2, a3);
        zp[1] = make_float4(a4, a5, a6, a7);
    }
    __syncthreads();
    if (t < 64) {
        int a = t >> 3, b = t & 7;
        float s = 0.0f;
        for (int i = 0; i < 96; i++)
            s += Ysh[i * 8 + a] * Zsh[i * 8 + b];
        W8[a * 8 + b] = s;
    }
    __syncthreads();
    if (t < 64) {
        int a = t >> 3, b = t & 7;
        T8[a * 9 + b] = 0.5f * (W8[a * 8 + b] + W8[b * 8 + a]);
    }
    if (t >= 32 && t < 96) {
        int e = t - 32;  // 64 entries
        int j = e >> 3, k = e & 7;
        V8[j * 9 + k] = (j == k) ? 1.0f : 0.0f;
    }
    __syncthreads();

    // g = Y' d  (warp1 lanes, concurrent with warp0's Jacobi below)
    if (t >= 32 && t < 40) {
        int a = t - 32;
        float s = 0.0f;
        for (int i = 0; i < 96; i++) s += Ysh[i * 8 + a] * dvec[i];
        gvec[a] = s;
    }

    // warp 0: 8x8 cyclic Jacobi with eigenvectors (7 sweeps, tournament)
    if (t < 32) {
        for (int sweep = 0; sweep < 7; sweep++) {
            for (int r = 0; r < 7; r++) {
                if (t < 4) {
                    int p, q;
                    if (t == 0) { p = 7; q = r; }
                    else { p = (r + t) % 7; q = (r + 7 - t) % 7; }
                    rp4[t] = p; rq4[t] = q;
                    float app = T8[p * 9 + p];
                    float aqq = T8[q * 9 + q];
                    float apq = T8[p * 9 + q];
                    float c = 1.0f, s = 0.0f;
                    if (fabsf(apq) > 1e-30f) {
                        float tau = (aqq - app) / (2.0f * apq);
                        float tt = (tau >= 0.0f)
                                       ? 1.0f / (tau + sqrtf(1.0f + tau * tau))
                                       : 1.0f / (tau - sqrtf(1.0f + tau * tau));
                        c = rsqrtf(1.0f + tt * tt);
                        s = tt * c;
                    }
                    rc4[t] = c; rs4[t] = s;
                }
                __syncwarp();
                // T: 16 independent 2x2 block rotations; V: column rotations
                if (t < 16) {
                    int a = t >> 2, b = t & 3;
                    int pa = rp4[a], qa = rq4[a];
                    int pb = rp4[b], qb = rq4[b];
                    float ca = rc4[a], sa = rs4[a];
                    float cb = rc4[b], sb = rs4[b];
                    float x00 = T8[pa * 9 + pb], x01 = T8[pa * 9 + qb];
                    float x10 = T8[qa * 9 + pb], x11 = T8[qa * 9 + qb];
                    float y00 = ca * x00 - sa * x10;
                    float y01 = ca * x01 - sa * x11;
                    float y10 = sa * x00 + ca * x10;
                    float y11 = sa * x01 + ca * x11;
                    T8[pa * 9 + pb] = cb * y00 - sb * y01;
                    T8[pa * 9 + qb] = sb * y00 + cb * y01;
                    T8[qa * 9 + pb] = cb * y10 - sb * y11;
                    T8[qa * 9 + qb] = sb * y10 + cb * y11;
                }
                {
                    int j = t >> 2, k = t & 3;   // 8 x 4
                    int p = rp4[k], q = rq4[k];
                    float c = rc4[k], s = rs4[k];
                    float vp = V8[j * 9 + p], vq = V8[j * 9 + q];
                    V8[j * 9 + p] = c * vp - s * vq;
                    V8[j * 9 + q] = s * vp + c * vq;
                }
                __syncwarp();
            }
        }
    }
    __syncthreads();

    if (t == 0) {
        int i0 = 0, i1 = -1, i2 = -1;
        float v0 = -1e30f, v1 = -1e30f, v2 = -1e30f;
#pragma unroll
        for (int i = 0; i < 8; i++) {
            float e = T8[i * 9 + i];
            if (e > v0)      { v2 = v1; i2 = i1; v1 = v0; i1 = i0; v0 = e; i0 = i; }
            else if (e > v1) { v2 = v1; i2 = i1; v1 = e;  i1 = i; }
            else if (e > v2) { v2 = e;  i2 = i; }
        }
        int idxs[3] = { i0, i1, i2 };
        float ssum = 0.0f;
#pragma unroll
        for (int k = 0; k < 3; k++) {
            float pr = 0.0f;
            for (int a = 0; a < 8; a++) pr += V8[a * 9 + idxs[k]] * gvec[a];
            ssum += pr * pr;
        }
        float sv2 = 0.0f;
        for (int v = 0; v < RES; v++) sv2 += g_sv[v] * g_sv[v];
        float dist_pca = sqrtf(sv2) * sqrtf(ssum);
        float pca_loss = 1.0f - dist_pca;

        float inter = (float)g_inter;
        float uni = 2048.0f - inter;   // reference: P + P - inter
        float iou_loss = 1.0f - inter / uni;

        out[0] = pca_loss + iou_loss;
    }
}

// -------------------- launcher --------------------
extern "C" void kernel_launch(void* const* d_in, const int* in_sizes, int n_in,
                              void* d_out, int out_size) {
    const float* pred  = (const float*)d_in[0];
    const float* label = (const float*)d_in[1];
    float* out = (float*)d_out;

    k_zero<<<1, 256>>>();
    k_basis<<<1, 32>>>();
    k_curves<<<NB, 96>>>(pred, label);
    k_means<<<128, 96>>>();
    k_cov<<<dim3(12, 16), 96>>>();
    k_eig<<<1, 96>>>(out);
}

// round 7
// speedup vs baseline: 17.4375x; 1.5514x over previous
#include <cuda_runtime.h>
#include <math.h>

#define NJ   68
#define RES  32
#define NB   2048
#define NROWS 4096
#define DIMX 96
#define KITER 32        // power iterations (ratio <=0.82 -> 0.82^32 ~ 1.8e-3)
#define EIG_THREADS 384
// dynamic smem: C(96*97) + Y(768) + Z(768) + P(4*96*8)
#define EIG_SMEM ((96 * 97 + 768 + 768 + 3072) * 4)

// -------------------- scratch (device globals; no allocs) --------------------
__device__ float  g_Nu[NJ * RES];
__device__ float  g_sv[RES];
__device__ float  g_X[NROWS * DIMX];
__device__ float  g_S[DIMX * DIMX];    // X^T X (un-centered, un-normalized)
__device__ double g_sumP[DIMX];
__device__ double g_sumL[DIMX];
__device__ unsigned long long g_inter;

// -------------------- K1: zero + basis matrices (fused) --------------------
__global__ void k_init() {
    int t = threadIdx.x;  // 256
    for (int i = t; i < DIMX * DIMX; i += 256) g_S[i] = 0.0f;
    if (t < DIMX) { g_sumP[t] = 0.0; g_sumL[t] = 0.0; }
    if (t == 0) g_inter = 0ull;

    int uj = t;
    if (uj >= RES) return;
    float u = (float)((double)uj / 31.0);
    {   // Nu: n=68, p=2, L=71, internal knots (i-2)/66
        const int L = NJ + 2 + 1;  // 71
        float kn[71];
        for (int i = 0; i < L; i++) {
            if (i < 3)            kn[i] = 0.0f;
            else if (i >= L - 3)  kn[i] = 1.0f;
            else                  kn[i] = (float)((double)(i - 2) / 66.0);
        }
        float N[70];
        for (int i = 0; i < L - 1; i++)
            N[i] = (kn[i] <= u && u < kn[i + 1]) ? 1.0f : 0.0f;
        for (int d = 1; d <= 2; d++) {
            int m = (L - 1) - d;
            for (int i = 0; i < m; i++) {
                float ld = kn[i + d] - kn[i];
                float rd = kn[i + d + 1] - kn[i + 1];
                float t1 = (ld == 0.0f) ? 0.0f : (u - kn[i]) / ld * N[i];
                float t2 = (rd == 0.0f) ? 0.0f : (kn[i + d + 1] - u) / rd * N[i + 1];
                N[i] = t1 + t2;
            }
        }
        for (int i = 0; i < NJ; i++) g_Nu[i * RES + uj] = N[i];
    }
    {   // Nv: n=68, q=3, L=72, internal knots (i-3)/65; only sv needed
        const int L = NJ + 3 + 1;  // 72
        float kn[72];
        for (int i = 0; i < L; i++) {
            if (i < 4)            kn[i] = 0.0f;
            else if (i >= L - 4)  kn[i] = 1.0f;
            else                  kn[i] = (float)((double)(i - 3) / 65.0);
        }
        float N[71];
        for (int i = 0; i < L - 1; i++)
            N[i] = (kn[i] <= u && u < kn[i + 1]) ? 1.0f : 0.0f;
        for (int d = 1; d <= 3; d++) {
            int m = (L - 1) - d;
            for (int i = 0; i < m; i++) {
                float ld = kn[i + d] - kn[i];
                float rd = kn[i + d + 1] - kn[i + 1];
                float t1 = (ld == 0.0f) ? 0.0f : (u - kn[i]) / ld * N[i];
                float t2 = (rd == 0.0f) ? 0.0f : (kn[i + d + 1] - u) / rd * N[i + 1];
                N[i] = t1 + t2;
            }
        }
        float s = 0.0f;
        for (int i = 0; i < NJ; i++) s += N[i];
        g_sv[uj] = s;
    }
}

// -------------------- K2: curves + IoU count -------------------------------
__global__ void k_curves(const float* __restrict__ pred,
                         const float* __restrict__ label) {
    __shared__ float sNu[NJ * RES];
    __shared__ float sP[NJ * 3], sL[NJ * 3];
    __shared__ float cP[DIMX], cL[DIMX];

    int b = blockIdx.x;
    int t = threadIdx.x;  // 96

    for (int i = t; i < NJ * RES; i += 96) sNu[i] = g_Nu[i];
    for (int i = t; i < NJ * 3; i += 96) {
        sP[i] = pred[b * (NJ * 3) + i];
        sL[i] = label[b * (NJ * 3) + i];
    }
    __syncthreads();

    int u = t / 3, c = t - u * 3;
    float aP = 0.0f, aL = 0.0f;
#pragma unroll 4
    for (int i = 0; i < NJ; i++) {
        float w = sNu[i * RES + u];
        aP += sP[i * 3 + c] * w;
        aL += sL[i * 3 + c] * w;
    }
    g_X[b * DIMX + t]        = aP;
    g_X[(NB + b) * DIMX + t] = aL;
    cP[t] = aP; cL[t] = aL;
    __syncthreads();

    if (t < 32) {
        float p0 = cP[t * 3], p1 = cP[t * 3 + 1], p2 = cP[t * 3 + 2];
        float l0 = cL[t * 3], l1 = cL[t * 3 + 1], l2 = cL[t * 3 + 2];
        int cnt = 0;
#pragma unroll
        for (int v = 0; v < RES; v++) {
            float sv = g_sv[v];
            float d0 = p0 * sv - l0 * sv;
            float d1 = p1 * sv - l1 * sv;
            float d2 = p2 * sv - l2 * sv;
            float s = (d0 * d0 + d1 * d1) + d2 * d2;
            cnt += (s < 0.25f) ? 1 : 0;
        }
#pragma unroll
        for (int o = 16; o > 0; o >>= 1)
            cnt += __shfl_down_sync(0xffffffffu, cnt, o);
        if (t == 0) atomicAdd(&g_inter, (unsigned long long)cnt);
    }
}

// -------------------- K3: X^T X Gram (uncentered) + column sums ------------
__global__ void k_xtx() {
    int rb = blockIdx.x * 8;   // gram row base (grid.x = 12)
    int ch = blockIdx.y;       // chunk (grid.y = 16)
    int t = threadIdx.x;       // 96

    float acc[8] = {0, 0, 0, 0, 0, 0, 0, 0};
    float colsum = 0.0f;
    int row0 = ch * 256;
    for (int i = 0; i < 256; i++) {
        const float* xrow = &g_X[(row0 + i) * DIMX];
        float xk = xrow[t];
        colsum += xk;
#pragma unroll
        for (int s = 0; s < 8; s++)
            acc[s] += xrow[rb + s] * xk;
    }
#pragma unroll
    for (int s = 0; s < 8; s++)
        atomicAdd(&g_S[(rb + s) * DIMX + t], acc[s]);
    if (blockIdx.x == 0) {
        if (ch < 8) atomicAdd(&g_sumP[t], (double)colsum);
        else        atomicAdd(&g_sumL[t], (double)colsum);
    }
}

// -------------------- K4: block power iteration + Rayleigh-Ritz ------------
// Top-3 eigenspace of C = (S - n mu mu^T)/(n-1). Top triple ~1.0 (exact
// decoupled Gram eigenvalue), lambda4 <= ~0.78 => ratio <= 0.82; K=32 gives
// ~2e-3 subspace angle, quadratically small in ssum. Rayleigh-Ritz on the
// 8-dim subspace resolves the near-degenerate triple exactly.
__global__ void __launch_bounds__(EIG_THREADS)
k_eig(float* __restrict__ out) {
    extern __shared__ float esm[];
    float* C = esm;                 // 96 x 97 (padded)
    float* Y = C + 96 * 97;         // 96 x 8
    float* Z = Y + 96 * 8;          // 96 x 8
    float* P = Z + 96 * 8;          // 4 x 96 x 8 partials
    __shared__ float S8[64], R8[64], Rinv[8], W8[64];
    __shared__ float T8[8 * 9], V8[8 * 9];
    __shared__ float rc4[4], rs4[4];
    __shared__ int   rp4[4], rq4[4];
    __shared__ float dvec[DIMX], mus[DIMX], gvec[8];

    const int t = threadIdx.x;
    const int r = t % 96;           // row
    const int g = t / 96;           // j-group 0..3

    if (t < DIMX) {
        double sp = g_sumP[t], sl = g_sumL[t];
        mus[t]  = (float)((sp + sl) / 4096.0);
        dvec[t] = (float)(sp / 2048.0 - sl / 2048.0);
    }
    __syncthreads();

    for (int idx = t; idx < 96 * 96; idx += EIG_THREADS) {
        int i = idx / 96, j = idx - i * 96;
        C[i * 97 + j] = (g_S[idx] - 4096.0f * mus[i] * mus[j]) * (1.0f / 4095.0f);
    }
    if (t < 96) {
#pragma unroll
        for (int s = 0; s < 8; s++)
            Y[t * 8 + s] = cosf(0.7f * (float)((t + 1) * (s + 1))) +
                           ((t == s) ? 0.05f : 0.0f);
    }
    __syncthreads();

#define MATVEC()                                                          \
    {                                                                     \
        float a0=0,a1=0,a2=0,a3=0,a4=0,a5=0,a6=0,a7=0;                    \
        int j0 = g * 24;                                                  \
        _Pragma("unroll 4")                                               \
        for (int jj = 0; jj < 24; jj++) {                                 \
            int j = j0 + jj;                                              \
            float c = C[r * 97 + j];                                      \
            float4 y0 = *(const float4*)&Y[j * 8];                        \
            float4 y1 = *(const float4*)&Y[j * 8 + 4];                    \
            a0 += c * y0.x; a1 += c * y0.y; a2 += c * y0.z; a3 += c * y0.w;\
            a4 += c * y1.x; a5 += c * y1.y; a6 += c * y1.z; a7 += c * y1.w;\
        }                                                                 \
        float4* pp = (float4*)&P[(g * 96 + r) * 8];                       \
        pp[0] = make_float4(a0, a1, a2, a3);                              \
        pp[1] = make_float4(a4, a5, a6, a7);                              \
    }                                                                     \
    __syncthreads();                                                      \
    {                                                                     \
        int rr = t >> 2;                                                  \
        int cp = (t & 3) * 2;                                             \
        float s0 = P[(0 * 96 + rr) * 8 + cp] + P[(1 * 96 + rr) * 8 + cp]  \
                 + P[(2 * 96 + rr) * 8 + cp] + P[(3 * 96 + rr) * 8 + cp]; \
        float s1 = P[(0 * 96 + rr) * 8 + cp + 1] + P[(1 * 96 + rr) * 8 + cp + 1] \
                 + P[(2 * 96 + rr) * 8 + cp + 1] + P[(3 * 96 + rr) * 8 + cp + 1];\
        Z[rr * 8 + cp] = s0; Z[rr * 8 + cp + 1] = s1;                     \
    }                                                                     \
    __syncthreads();

// Gram of columns of SRC (96x8) into S8, 256 threads (64 pairs x 4-way split)
#define GRAM8(SRC)                                                        \
    if (t < 256) {                                                        \
        int pair = t >> 2, sub = t & 3;                                   \
        int a = pair >> 3, b = pair & 7;                                  \
        float s = 0.0f;                                                   \
        for (int i = sub * 24; i < sub * 24 + 24; i++)                    \
            s += SRC[i * 8 + a] * SRC[i * 8 + b];                         \
        s += __shfl_down_sync(0xffffffffu, s, 1);                         \
        s += __shfl_down_sync(0xffffffffu, s, 2);                         \
        if (sub == 0) S8[pair] = s;                                       \
    }                                                                     \
    __syncthreads();

#define CHOL8()                                                           \
    if (t == 0) {                                                         \
        _Pragma("unroll")                                                 \
        for (int k = 0; k < 8; k++) {                                     \
            float dk = sqrtf(fmaxf(S8[k * 8 + k], 1e-30f));               \
            float inv = 1.0f / dk;                                        \
            R8[k * 8 + k] = dk; Rinv[k] = inv;                            \
            for (int j = k + 1; j < 8; j++)                               \
                R8[k * 8 + j] = S8[k * 8 + j] * inv;                      \
            for (int i = k + 1; i < 8; i++)                               \
                for (int j = i; j < 8; j++)                               \
                    S8[i * 8 + j] -= R8[k * 8 + i] * R8[k * 8 + j];       \
        }                                                                 \
    }                                                                     \
    __syncthreads();

// row-wise back-solve: DST = SRC * R^-1 (t < 96, one row each)
#define RSOLVE(SRC, DST)                                                  \
    if (t < 96) {                                                         \
        float z[8], y[8];                                                 \
        _Pragma("unroll")                                                 \
        for (int s = 0; s < 8; s++) z[s] = SRC[t * 8 + s];                \
        _Pragma("unroll")                                                 \
        for (int s = 0; s < 8; s++) {                                     \
            float v = z[s];                                               \
            for (int k = 0; k < s; k++) v -= y[k] * R8[k * 8 + s];        \
            y[s] = v * Rinv[s];                                           \
        }                                                                 \
        _Pragma("unroll")                                                 \
        for (int s = 0; s < 8; s++) DST[t * 8 + s] = y[s];                \
    }                                                                     \
    __syncthreads();

    for (int it = 0; it < KITER; it++) {
        MATVEC();
        if ((it + 1) % 6 == 0) {
            GRAM8(Z);
            CHOL8();
            RSOLVE(Z, Y);
        } else {
            if (t < 192) {   // Y = Z (768 floats as 192 float4)
                ((float4*)Y)[t] = ((const float4*)Z)[t];
            }
            __syncthreads();
        }
    }

    // final orthonormalization of Y
    GRAM8(Y);
    CHOL8();
    RSOLVE(Y, Y);

    // Z = C*Y for Rayleigh-Ritz
    MATVEC();

    // W8 = Y' Z
    if (t < 256) {
        int pair = t >> 2, sub = t & 3;
        int a = pair >> 3, b = pair & 7;
        float s = 0.0f;
        for (int i = sub * 24; i < sub * 24 + 24; i++)
            s += Y[i * 8 + a] * Z[i * 8 + b];
        s += __shfl_down_sync(0xffffffffu, s, 1);
        s += __shfl_down_sync(0xffffffffu, s, 2);
        if (sub == 0) W8[pair] = s;
    }
    __syncthreads();
    if (t < 64) {
        int a = t >> 3, b = t & 7;
        T8[a * 9 + b] = 0.5f * (W8[a * 8 + b] + W8[b * 8 + a]);
    }
    if (t >= 64 && t < 128) {
        int e = t - 64;
        int j = e >> 3, k = e & 7;
        V8[j * 9 + k] = (j == k) ? 1.0f : 0.0f;
    }
    __syncthreads();

    // g = Y' d (warp1, concurrent with warp0's Jacobi)
    if (t >= 32 && t < 40) {
        int a = t - 32;
        float s = 0.0f;
        for (int i = 0; i < 96; i++) s += Y[i * 8 + a] * dvec[i];
        gvec[a] = s;
    }

    // warp 0: 8x8 cyclic Jacobi with eigenvectors (7 sweeps, tournament)
    if (t < 32) {
        for (int sweep = 0; sweep < 7; sweep++) {
            for (int rr = 0; rr < 7; rr++) {
                if (t < 4) {
                    int p, q;
                    if (t == 0) { p = 7; q = rr; }
                    else { p = (rr + t) % 7; q = (rr + 7 - t) % 7; }
                    rp4[t] = p; rq4[t] = q;
                    float app = T8[p * 9 + p];
                    float aqq = T8[q * 9 + q];
                    float apq = T8[p * 9 + q];
                    float c = 1.0f, s = 0.0f;
                    if (fabsf(apq) > 1e-30f) {
                        float tau = (aqq - app) / (2.0f * apq);
                        float tt = (tau >= 0.0f)
                                       ? 1.0f / (tau + sqrtf(1.0f + tau * tau))
                                       : 1.0f / (tau - sqrtf(1.0f + tau * tau));
                        c = rsqrtf(1.0f + tt * tt);
                        s = tt * c;
                    }
                    rc4[t] = c; rs4[t] = s;
                }
                __syncwarp();
                if (t < 16) {
                    int a = t >> 2, b = t & 3;
                    int pa = rp4[a], qa = rq4[a];
                    int pb = rp4[b], qb = rq4[b];
                    float ca = rc4[a], sa = rs4[a];
                    float cb = rc4[b], sb = rs4[b];
                    float x00 = T8[pa * 9 + pb], x01 = T8[pa * 9 + qb];
                    float x10 = T8[qa * 9 + pb], x11 = T8[qa * 9 + qb];
                    float y00 = ca * x00 - sa * x10;
                    float y01 = ca * x01 - sa * x11;
                    float y10 = sa * x00 + ca * x10;
                    float y11 = sa * x01 + ca * x11;
                    T8[pa * 9 + pb] = cb * y00 - sb * y01;
                    T8[pa * 9 + qb] = sb * y00 + cb * y01;
                    T8[qa * 9 + pb] = cb * y10 - sb * y11;
                    T8[qa * 9 + qb] = sb * y10 + cb * y11;
                }
                {
                    int j = t >> 2, k = t & 3;
                    int p = rp4[k], q = rq4[k];
                    float c = rc4[k], s = rs4[k];
                    float vp = V8[j * 9 + p], vq = V8[j * 9 + q];
                    V8[j * 9 + p] = c * vp - s * vq;
                    V8[j * 9 + q] = s * vp + c * vq;
                }
                __syncwarp();
            }
        }
    }
    __syncthreads();

    if (t == 0) {
        int i0 = 0, i1 = -1, i2 = -1;
        float v0 = -1e30f, v1 = -1e30f, v2 = -1e30f;
#pragma unroll
        for (int i = 0; i < 8; i++) {
            float e = T8[i * 9 + i];
            if (e > v0)      { v2 = v1; i2 = i1; v1 = v0; i1 = i0; v0 = e; i0 = i; }
            else if (e > v1) { v2 = v1; i2 = i1; v1 = e;  i1 = i; }
            else if (e > v2) { v2 = e;  i2 = i; }
        }
        int idxs[3] = { i0, i1, i2 };
        float ssum = 0.0f;
#pragma unroll
        for (int k = 0; k < 3; k++) {
            float pr = 0.0f;
            for (int a = 0; a < 8; a++) pr += V8[a * 9 + idxs[k]] * gvec[a];
            ssum += pr * pr;
        }
        float sv2 = 0.0f;
        for (int v = 0; v < RES; v++) sv2 += g_sv[v] * g_sv[v];
        float dist_pca = sqrtf(sv2) * sqrtf(ssum);
        float pca_loss = 1.0f - dist_pca;

        float inter = (float)g_inter;
        float uni = 2048.0f - inter;   // reference: P + P - inter
        float iou_loss = 1.0f - inter / uni;

        out[0] = pca_loss + iou_loss;
    }
}

// -------------------- launcher --------------------
extern "C" void kernel_launch(void* const* d_in, const int* in_sizes, int n_in,
                              void* d_out, int out_size) {
    const float* pred  = (const float*)d_in[0];
    const float* label = (const float*)d_in[1];
    float* out = (float*)d_out;

    cudaFuncSetAttribute(k_eig, cudaFuncAttributeMaxDynamicSharedMemorySize,
                         EIG_SMEM);

    k_init<<<1, 256>>>();
    k_curves<<<NB, 96>>>(pred, label);
    k_xtx<<<dim3(12, 16), 96>>>();
    k_eig<<<1, EIG_THREADS, EIG_SMEM>>>(out);
}

// round 9
// speedup vs baseline: 20.5259x; 1.1771x over previous
#include <cuda_runtime.h>
#include <math.h>

#define NJ   68
#define RES  32
#define NB   2048
#define NROWS 4096
#define DIMX 96
#define EIG_THREADS 384
#define CHEB_B 0.85f
#define CHEB_DEG 5      // per stage
#define CHEB_STAGES 3
// dynamic smem: C(96*97) + Y0(768) + Y1(768) + P(4*96*8)
#define EIG_SMEM ((96 * 97 + 768 + 768 + 3072) * 4)

// -------------------- scratch (device globals; no allocs) --------------------
__device__ float  g_Nu[NJ * RES];
__device__ float  g_sv[RES];
__device__ float  g_X[NROWS * DIMX];
__device__ float  g_S[DIMX * DIMX];    // X^T X (un-centered, un-normalized)
__device__ double g_sumP[DIMX];
__device__ double g_sumL[DIMX];
__device__ unsigned long long g_inter;

// -------------------- K1: zero + basis matrices (fused) --------------------
__global__ void k_init() {
    int t = threadIdx.x;  // 256
    for (int i = t; i < DIMX * DIMX; i += 256) g_S[i] = 0.0f;
    if (t < DIMX) { g_sumP[t] = 0.0; g_sumL[t] = 0.0; }
    if (t == 0) g_inter = 0ull;

    int uj = t;
    if (uj >= RES) return;
    float u = (float)((double)uj / 31.0);
    {   // Nu: n=68, p=2, L=71, internal knots (i-2)/66
        const int L = NJ + 2 + 1;  // 71
        float kn[71];
        for (int i = 0; i < L; i++) {
            if (i < 3)            kn[i] = 0.0f;
            else if (i >= L - 3)  kn[i] = 1.0f;
            else                  kn[i] = (float)((double)(i - 2) / 66.0);
        }
        float N[70];
        for (int i = 0; i < L - 1; i++)
            N[i] = (kn[i] <= u && u < kn[i + 1]) ? 1.0f : 0.0f;
        for (int d = 1; d <= 2; d++) {
            int m = (L - 1) - d;
            for (int i = 0; i < m; i++) {
                float ld = kn[i + d] - kn[i];
                float rd = kn[i + d + 1] - kn[i + 1];
                float t1 = (ld == 0.0f) ? 0.0f : (u - kn[i]) / ld * N[i];
                float t2 = (rd == 0.0f) ? 0.0f : (kn[i + d + 1] - u) / rd * N[i + 1];
                N[i] = t1 + t2;
            }
        }
        for (int i = 0; i < NJ; i++) g_Nu[i * RES + uj] = N[i];
    }
    {   // Nv: n=68, q=3, L=72, internal knots (i-3)/65; only sv needed
        const int L = NJ + 3 + 1;  // 72
        float kn[72];
        for (int i = 0; i < L; i++) {
            if (i < 4)            kn[i] = 0.0f;
            else if (i >= L - 4)  kn[i] = 1.0f;
            else                  kn[i] = (float)((double)(i - 3) / 65.0);
        }
        float N[71];
        for (int i = 0; i < L - 1; i++)
            N[i] = (kn[i] <= u && u < kn[i + 1]) ? 1.0f : 0.0f;
        for (int d = 1; d <= 3; d++) {
            int m = (L - 1) - d;
            for (int i = 0; i < m; i++) {
                float ld = kn[i + d] - kn[i];
                float rd = kn[i + d + 1] - kn[i + 1];
                float t1 = (ld == 0.0f) ? 0.0f : (u - kn[i]) / ld * N[i];
                float t2 = (rd == 0.0f) ? 0.0f : (kn[i + d + 1] - u) / rd * N[i + 1];
                N[i] = t1 + t2;
            }
        }
        float s = 0.0f;
        for (int i = 0; i < NJ; i++) s += N[i];
        g_sv[uj] = s;
    }
}

// -------------------- K2: curves + IoU, 4 batches per block -----------------
__global__ void __launch_bounds__(384)
k_curves(const float* __restrict__ pred, const float* __restrict__ label) {
    __shared__ float sNu[NJ * RES];
    __shared__ float sP[4][NJ * 3], sL[4][NJ * 3];
    __shared__ float cP[4][DIMX], cL[4][DIMX];

    int t = threadIdx.x;       // 384
    int sub = t / 96;          // batch within block 0..3
    int tt = t - sub * 96;     // 0..95
    int b = blockIdx.x * 4 + sub;

    for (int i = t; i < NJ * RES; i += 384) sNu[i] = g_Nu[i];
    for (int i = tt; i < NJ * 3; i += 96) {
        sP[sub][i] = pred[b * (NJ * 3) + i];
        sL[sub][i] = label[b * (NJ * 3) + i];
    }
    __syncthreads();

    int u = tt / 3, c = tt - u * 3;
    float aP = 0.0f, aL = 0.0f;
#pragma unroll 4
    for (int i = 0; i < NJ; i++) {
        float w = sNu[i * RES + u];
        aP += sP[sub][i * 3 + c] * w;
        aL += sL[sub][i * 3 + c] * w;
    }
    g_X[b * DIMX + tt]        = aP;
    g_X[(NB + b) * DIMX + tt] = aL;
    cP[sub][tt] = aP; cL[sub][tt] = aL;
    __syncthreads();

    if (tt < 32) {   // t = sub*96 + 0..31: aligned full warp per sub
        float p0 = cP[sub][tt * 3], p1 = cP[sub][tt * 3 + 1], p2 = cP[sub][tt * 3 + 2];
        float l0 = cL[sub][tt * 3], l1 = cL[sub][tt * 3 + 1], l2 = cL[sub][tt * 3 + 2];
        int cnt = 0;
#pragma unroll
        for (int v = 0; v < RES; v++) {
            float sv = g_sv[v];
            float d0 = p0 * sv - l0 * sv;
            float d1 = p1 * sv - l1 * sv;
            float d2 = p2 * sv - l2 * sv;
            float s = (d0 * d0 + d1 * d1) + d2 * d2;
            cnt += (s < 0.25f) ? 1 : 0;
        }
#pragma unroll
        for (int o = 16; o > 0; o >>= 1)
            cnt += __shfl_down_sync(0xffffffffu, cnt, o);
        if (tt == 0) atomicAdd(&g_inter, (unsigned long long)cnt);
    }
}

// -------------------- K3: X^T X Gram (uncentered) + column sums ------------
__global__ void k_xtx() {
    int rb = blockIdx.x * 8;   // gram row base (grid.x = 12)
    int ch = blockIdx.y;       // chunk (grid.y = 16)
    int t = threadIdx.x;       // 96

    float acc[8] = {0, 0, 0, 0, 0, 0, 0, 0};
    float colsum = 0.0f;
    int row0 = ch * 256;
    for (int i = 0; i < 256; i++) {
        const float* xrow = &g_X[(row0 + i) * DIMX];
        float xk = xrow[t];
        colsum += xk;
#pragma unroll
        for (int s = 0; s < 8; s++)
            acc[s] += xrow[rb + s] * xk;
    }
#pragma unroll
    for (int s = 0; s < 8; s++)
        atomicAdd(&g_S[(rb + s) * DIMX + t], acc[s]);
    if (blockIdx.x == 0) {
        if (ch < 8) atomicAdd(&g_sumP[t], (double)colsum);
        else        atomicAdd(&g_sumL[t], (double)colsum);
    }
}

// -------------------- K4: Chebyshev-filtered subspace + Rayleigh-Ritz ------
// Top-3 eigenspace of C = (S - n mu mu^T)/(n-1). Top triple ~1.0, lambda4
// <= ~0.80. Band [0, 0.85]: T5 amplifies the triple 17-67x per stage vs <=1
// in-band. THREE degree-5 stages, CholQR after each: per-stage Gram cond
// <= ~4.5e3 (fp32-safe; degree 10 NaN'd via rank-collapse -> Inf Gram).
// Ridge 1e-6*tr on the Gram guards Cholesky; span is R-invariant.
__global__ void __launch_bounds__(EIG_THREADS)
k_eig(float* __restrict__ out) {
    extern __shared__ float esm[];
    float* C  = esm;            // 96 x 97 (padded)
    float* Y0 = C + 96 * 97;    // 96 x 8
    float* Y1 = Y0 + 96 * 8;    // 96 x 8
    float* P  = Y1 + 96 * 8;    // 4 x 96 x 8 partials
    __shared__ float S8[64], R8[64], Rinv[8], W8[64];
    __shared__ float T8[8 * 9], V8[8 * 9];
    __shared__ float rc4[4], rs4[4];
    __shared__ int   rp4[4], rq4[4];
    __shared__ float dvec[DIMX], mus[DIMX], gvec[8];

    const int t = threadIdx.x;
    const int r = t % 96;           // row
    const int g = t / 96;           // j-group 0..3

    if (t < DIMX) {
        double sp = g_sumP[t], sl = g_sumL[t];
        mus[t]  = (float)((sp + sl) / 4096.0);
        dvec[t] = (float)(sp / 2048.0 - sl / 2048.0);
    }
    __syncthreads();

    for (int idx = t; idx < 96 * 96; idx += EIG_THREADS) {
        int i = idx / 96, j = idx - i * 96;
        C[i * 97 + j] = (g_S[idx] - 4096.0f * mus[i] * mus[j]) * (1.0f / 4095.0f);
    }
    if (t < 96) {
#pragma unroll
        for (int s = 0; s < 8; s++)
            Y0[t * 8 + s] = cosf(0.7f * (float)((t + 1) * (s + 1))) +
                            ((t == s) ? 0.05f : 0.0f);
    }
    __syncthreads();

    float* cur = Y0;
    float* prv = Y1;

#define MATVEC(SRC)                                                       \
    {                                                                     \
        float a0=0,a1=0,a2=0,a3=0,a4=0,a5=0,a6=0,a7=0;                    \
        int j0 = g * 24;                                                  \
        _Pragma("unroll 4")                                               \
        for (int jj = 0; jj < 24; jj++) {                                 \
            int j = j0 + jj;                                              \
            float c = C[r * 97 + j];                                      \
            float4 y0 = *(const float4*)&SRC[j * 8];                      \
            float4 y1 = *(const float4*)&SRC[j * 8 + 4];                  \
            a0 += c * y0.x; a1 += c * y0.y; a2 += c * y0.z; a3 += c * y0.w;\
            a4 += c * y1.x; a5 += c * y1.y; a6 += c * y1.z; a7 += c * y1.w;\
        }                                                                 \
        float4* pp = (float4*)&P[(g * 96 + r) * 8];                       \
        pp[0] = make_float4(a0, a1, a2, a3);                              \
        pp[1] = make_float4(a4, a5, a6, a7);                              \
    }                                                                     \
    __syncthreads();

#define REDUCE3(ca, cb, cc, CUR, PRV, DST)                                \
    {                                                                     \
        _Pragma("unroll")                                                 \
        for (int h = 0; h < 2; h++) {                                     \
            int e = t + h * 384;                                          \
            float cy = P[e] + P[768 + e] + P[1536 + e] + P[2304 + e];     \
            DST[e] = (ca) * cy + (cb) * CUR[e] + (cc) * PRV[e];           \
        }                                                                 \
    }                                                                     \
    __syncthreads();

#define REDUCE2(ca, cb, CUR, DST)                                         \
    {                                                                     \
        _Pragma("unroll")                                                 \
        for (int h = 0; h < 2; h++) {                                     \
            int e = t + h * 384;                                          \
            float cy = P[e] + P[768 + e] + P[1536 + e] + P[2304 + e];     \
            DST[e] = (ca) * cy + (cb) * CUR[e];                           \
        }                                                                 \
    }                                                                     \
    __syncthreads();

#define GRAM8(SRC)                                                        \
    if (t < 256) {                                                        \
        int pair = t >> 2, sub = t & 3;                                   \
        int a = pair >> 3, b = pair & 7;                                  \
        float s = 0.0f;                                                   \
        for (int i = sub * 24; i < sub * 24 + 24; i++)                    \
            s += SRC[i * 8 + a] * SRC[i * 8 + b];                         \
        s += __shfl_down_sync(0xffffffffu, s, 1);                         \
        s += __shfl_down_sync(0xffffffffu, s, 2);                         \
        if (sub == 0) S8[pair] = s;                                       \
    }                                                                     \
    __syncthreads();

// Cholesky with ridge: S += 1e-6*tr(S)*I. Any invertible R preserves span.
#define CHOL8()                                                           \
    if (t == 0) {                                                         \
        float tr = 0.0f;                                                  \
        _Pragma("unroll")                                                 \
        for (int k = 0; k < 8; k++) tr += S8[k * 8 + k];                  \
        float ridge = 1e-6f * tr;                                         \
        _Pragma("unroll")                                                 \
        for (int k = 0; k < 8; k++) S8[k * 8 + k] += ridge;               \
        _Pragma("unroll")                                                 \
        for (int k = 0; k < 8; k++) {                                     \
            float dk = sqrtf(fmaxf(S8[k * 8 + k], 1e-30f));               \
            float inv = 1.0f / dk;                                        \
            R8[k * 8 + k] = dk; Rinv[k] = inv;                            \
            for (int j = k + 1; j < 8; j++)                               \
                R8[k * 8 + j] = S8[k * 8 + j] * inv;                      \
            for (int i = k + 1; i < 8; i++)                               \
                for (int j = i; j < 8; j++)                               \
                    S8[i * 8 + j] -= R8[k * 8 + i] * R8[k * 8 + j];       \
        }                                                                 \
    }                                                                     \
    __syncthreads();

#define RSOLVE(SRC, DST)                                                  \
    if (t < 96) {                                                         \
        float z[8], y[8];                                                 \
        _Pragma("unroll")                                                 \
        for (int s = 0; s < 8; s++) z[s] = SRC[t * 8 + s];                \
        _Pragma("unroll")                                                 \
        for (int s = 0; s < 8; s++) {                                     \
            float v = z[s];                                               \
            for (int k = 0; k < s; k++) v -= y[k] * R8[k * 8 + s];        \
            y[s] = v * Rinv[s];                                           \
        }                                                                 \
        _Pragma("unroll")                                                 \
        for (int s = 0; s < 8; s++) DST[t * 8 + s] = y[s];                \
    }                                                                     \
    __syncthreads();

    const float c1 = 2.0f / CHEB_B;   // init step:  Y1 = (2/b) C Y0 - Y0
    const float c4 = 4.0f / CHEB_B;   // recurrence: Yn = (4/b) C Yk - 2 Yk - Yp

    for (int stage = 0; stage < CHEB_STAGES; stage++) {
        MATVEC(cur);
        REDUCE2(c1, -1.0f, cur, prv);
        { float* tmp = cur; cur = prv; prv = tmp; }
        for (int k = 0; k < CHEB_DEG - 1; k++) {
            MATVEC(cur);
            REDUCE3(c4, -2.0f, -1.0f, cur, prv, prv);
            { float* tmp = cur; cur = prv; prv = tmp; }
        }
        GRAM8(cur);
        CHOL8();
        RSOLVE(cur, cur);
    }

    // Z = C*Y for Rayleigh-Ritz (Z lands in prv, cur untouched)
    MATVEC(cur);
    REDUCE2(1.0f, 0.0f, cur, prv);

    // W8 = cur' * prv
    if (t < 256) {
        int pair = t >> 2, sub = t & 3;
        int a = pair >> 3, b = pair & 7;
        float s = 0.0f;
        for (int i = sub * 24; i < sub * 24 + 24; i++)
            s += cur[i * 8 + a] * prv[i * 8 + b];
        s += __shfl_down_sync(0xffffffffu, s, 1);
        s += __shfl_down_sync(0xffffffffu, s, 2);
        if (sub == 0) W8[pair] = s;
    }
    __syncthreads();
    if (t < 64) {
        int a = t >> 3, b = t & 7;
        T8[a * 9 + b] = 0.5f * (W8[a * 8 + b] + W8[b * 8 + a]);
    }
    if (t >= 64 && t < 128) {
        int e = t - 64;
        int j = e >> 3, k = e & 7;
        V8[j * 9 + k] = (j == k) ? 1.0f : 0.0f;
    }
    __syncthreads();

    // g = Y' d (warp1, concurrent with warp0's Jacobi)
    if (t >= 32 && t < 40) {
        int a = t - 32;
        float s = 0.0f;
        for (int i = 0; i < 96; i++) s += cur[i * 8 + a] * dvec[i];
        gvec[a] = s;
    }

    // warp 0: 8x8 cyclic Jacobi with eigenvectors (7 sweeps, tournament)
    if (t < 32) {
        for (int sweep = 0; sweep < 7; sweep++) {
            for (int rr = 0; rr < 7; rr++) {
                if (t < 4) {
                    int p, q;
                    if (t == 0) { p = 7; q = rr; }
                    else { p = (rr + t) % 7; q = (rr + 7 - t) % 7; }
                    rp4[t] = p; rq4[t] = q;
                    float app = T8[p * 9 + p];
                    float aqq = T8[q * 9 + q];
                    float apq = T8[p * 9 + q];
                    float c = 1.0f, s = 0.0f;
                    if (fabsf(apq) > 1e-30f) {
                        float tau = (aqq - app) / (2.0f * apq);
                        float tt = (tau >= 0.0f)
                                       ? 1.0f / (tau + sqrtf(1.0f + tau * tau))
                                       : 1.0f / (tau - sqrtf(1.0f + tau * tau));
                        c = rsqrtf(1.0f + tt * tt);
                        s = tt * c;
                    }
                    rc4[t] = c; rs4[t] = s;
                }
                __syncwarp();
                if (t < 16) {
                    int a = t >> 2, b = t & 3;
                    int pa = rp4[a], qa = rq4[a];
                    int pb = rp4[b], qb = rq4[b];
                    float ca = rc4[a], sa = rs4[a];
                    float cb = rc4[b], sb = rs4[b];
                    float x00 = T8[pa * 9 + pb], x01 = T8[pa * 9 + qb];
                    float x10 = T8[qa * 9 + pb], x11 = T8[qa * 9 + qb];
                    float y00 = ca * x00 - sa * x10;
                    float y01 = ca * x01 - sa * x11;
                    float y10 = sa * x00 + ca * x10;
                    float y11 = sa * x01 + ca * x11;
                    T8[pa * 9 + pb] = cb * y00 - sb * y01;
                    T8[pa * 9 + qb] = sb * y00 + cb * y01;
                    T8[qa * 9 + pb] = cb * y10 - sb * y11;
                    T8[qa * 9 + qb] = sb * y10 + cb * y11;
                }
                {
                    int j = t >> 2, k = t & 3;
                    int p = rp4[k], q = rq4[k];
                    float c = rc4[k], s = rs4[k];
                    float vp = V8[j * 9 + p], vq = V8[j * 9 + q];
                    V8[j * 9 + p] = c * vp - s * vq;
                    V8[j * 9 + q] = s * vp + c * vq;
                }
                __syncwarp();
            }
        }
    }
    __syncthreads();

    if (t == 0) {
        int i0 = 0, i1 = -1, i2 = -1;
        float v0 = -1e30f, v1 = -1e30f, v2 = -1e30f;
#pragma unroll
        for (int i = 0; i < 8; i++) {
            float e = T8[i * 9 + i];
            if (e > v0)      { v2 = v1; i2 = i1; v1 = v0; i1 = i0; v0 = e; i0 = i; }
            else if (e > v1) { v2 = v1; i2 = i1; v1 = e;  i1 = i; }
            else if (e > v2) { v2 = e;  i2 = i; }
        }
        int idxs[3] = { i0, i1, i2 };
        float ssum = 0.0f;
#pragma unroll
        for (int k = 0; k < 3; k++) {
            float pr = 0.0f;
            for (int a = 0; a < 8; a++) pr += V8[a * 9 + idxs[k]] * gvec[a];
            ssum += pr * pr;
        }
        float sv2 = 0.0f;
        for (int v = 0; v < RES; v++) sv2 += g_sv[v] * g_sv[v];
        float dist_pca = sqrtf(sv2) * sqrtf(ssum);
        float pca_loss = 1.0f - dist_pca;

        float inter = (float)g_inter;
        float uni = 2048.0f - inter;   // reference: P + P - inter
        float iou_loss = 1.0f - inter / uni;

        out[0] = pca_loss + iou_loss;
    }
}

// -------------------- launcher --------------------
extern "C" void kernel_launch(void* const* d_in, const int* in_sizes, int n_in,
                              void* d_out, int out_size) {
    const float* pred  = (const float*)d_in[0];
    const float* label = (const float*)d_in[1];
    float* out = (float*)d_out;

    cudaFuncSetAttribute(k_eig, cudaFuncAttributeMaxDynamicSharedMemorySize,
                         EIG_SMEM);

    k_init<<<1, 256>>>();
    k_curves<<<512, 384>>>(pred, label);
    k_xtx<<<dim3(12, 16), 96>>>();
    k_eig<<<1, EIG_THREADS, EIG_SMEM>>>(out);
}

// round 11
// speedup vs baseline: 30.0040x; 1.4618x over previous
#include <cuda_runtime.h>
#include <math.h>

#define NJ   68
#define RES  32
#define NB   2048
#define NROWS 4096
#define DIMX 96
#define EIG_THREADS 384
#define CHEB_B 0.85f
#define CHEB_DEG 5      // per stage
#define CHEB_STAGES 3
// dynamic smem: C(96*97) + Y0(384) + Y1(384) + P(4*96*4)
#define EIG_SMEM ((96 * 97 + 384 + 384 + 1536) * 4)

// -------------------- scratch (device globals; no allocs) --------------------
__device__ float  g_Nu[NJ * RES];
__device__ float  g_sv[RES];
__device__ float  g_X[NROWS * DIMX];
__device__ float  g_S[DIMX * DIMX];    // X^T X (un-centered, un-normalized)
__device__ double g_sumP[DIMX];
__device__ double g_sumL[DIMX];
__device__ unsigned long long g_inter;

// compile-time knot vectors (match reference: float((i-p)/double(denom)))
__device__ __host__ constexpr float knotU(int i) {   // n=68,p=2,L=71
    return (i < 3) ? 0.0f : ((i >= 68) ? 1.0f : (float)((double)(i - 2) / 66.0));
}
__device__ __host__ constexpr float knotV(int i) {   // n=68,q=3,L=72
    return (i < 4) ? 0.0f : ((i >= 68) ? 1.0f : (float)((double)(i - 3) / 65.0));
}

// -------------------- K1: zero + basis matrices (register-resident) --------
__global__ void k_init() {
    int t = threadIdx.x;  // 256
    for (int i = t; i < DIMX * DIMX; i += 256) g_S[i] = 0.0f;
    if (t < DIMX) { g_sumP[t] = 0.0; g_sumL[t] = 0.0; }
    if (t == 0) g_inter = 0ull;

    int uj = t;
    if (uj >= RES) return;
    float u = (float)((double)uj / 31.0);

    {   // Nu (p=2): fully unrolled, knots are compile-time constants
        float N[70];
#pragma unroll
        for (int i = 0; i < 70; i++)
            N[i] = (knotU(i) <= u && u < knotU(i + 1)) ? 1.0f : 0.0f;
#pragma unroll
        for (int d = 1; d <= 2; d++) {
#pragma unroll
            for (int i = 0; i < 69; i++) {
                if (i < 70 - d) {
                    const float ld = knotU(i + d) - knotU(i);
                    const float rd = knotU(i + d + 1) - knotU(i + 1);
                    float t1 = (ld == 0.0f) ? 0.0f : (u - knotU(i)) / ld * N[i];
                    float t2 = (rd == 0.0f) ? 0.0f : (knotU(i + d + 1) - u) / rd * N[i + 1];
                    N[i] = t1 + t2;
                }
            }
        }
#pragma unroll
        for (int i = 0; i < NJ; i++) g_Nu[i * RES + uj] = N[i];
    }
    {   // Nv (q=3): only the column sum sv is needed
        float N[71];
#pragma unroll
        for (int i = 0; i < 71; i++)
            N[i] = (knotV(i) <= u && u < knotV(i + 1)) ? 1.0f : 0.0f;
#pragma unroll
        for (int d = 1; d <= 3; d++) {
#pragma unroll
            for (int i = 0; i < 70; i++) {
                if (i < 71 - d) {
                    const float ld = knotV(i + d) - knotV(i);
                    const float rd = knotV(i + d + 1) - knotV(i + 1);
                    float t1 = (ld == 0.0f) ? 0.0f : (u - knotV(i)) / ld * N[i];
                    float t2 = (rd == 0.0f) ? 0.0f : (knotV(i + d + 1) - u) / rd * N[i + 1];
                    N[i] = t1 + t2;
                }
            }
        }
        float s = 0.0f;
#pragma unroll
        for (int i = 0; i < NJ; i++) s += N[i];
        g_sv[uj] = s;
    }
}

// -------------------- K2: curves + IoU, 4 batches per block -----------------
__global__ void __launch_bounds__(384)
k_curves(const float* __restrict__ pred, const float* __restrict__ label) {
    __shared__ float sNu[NJ * RES];
    __shared__ float sP[4][NJ * 3], sL[4][NJ * 3];
    __shared__ float cP[4][DIMX], cL[4][DIMX];

    int t = threadIdx.x;       // 384
    int sub = t / 96;          // batch within block 0..3
    int tt = t - sub * 96;     // 0..95
    int b = blockIdx.x * 4 + sub;

    for (int i = t; i < NJ * RES; i += 384) sNu[i] = g_Nu[i];
    for (int i = tt; i < NJ * 3; i += 96) {
        sP[sub][i] = pred[b * (NJ * 3) + i];
        sL[sub][i] = label[b * (NJ * 3) + i];
    }
    __syncthreads();

    int u = tt / 3, c = tt - u * 3;
    float aP = 0.0f, aL = 0.0f;
#pragma unroll 4
    for (int i = 0; i < NJ; i++) {
        float w = sNu[i * RES + u];
        aP += sP[sub][i * 3 + c] * w;
        aL += sL[sub][i * 3 + c] * w;
    }
    g_X[b * DIMX + tt]        = aP;
    g_X[(NB + b) * DIMX + tt] = aL;
    cP[sub][tt] = aP; cL[sub][tt] = aL;
    __syncthreads();

    if (tt < 32) {   // t = sub*96 + 0..31: aligned full warp per sub
        float p0 = cP[sub][tt * 3], p1 = cP[sub][tt * 3 + 1], p2 = cP[sub][tt * 3 + 2];
        float l0 = cL[sub][tt * 3], l1 = cL[sub][tt * 3 + 1], l2 = cL[sub][tt * 3 + 2];
        int cnt = 0;
#pragma unroll
        for (int v = 0; v < RES; v++) {
            float sv = g_sv[v];
            float d0 = p0 * sv - l0 * sv;
            float d1 = p1 * sv - l1 * sv;
            float d2 = p2 * sv - l2 * sv;
            float s = (d0 * d0 + d1 * d1) + d2 * d2;
            cnt += (s < 0.25f) ? 1 : 0;
        }
#pragma unroll
        for (int o = 16; o > 0; o >>= 1)
            cnt += __shfl_down_sync(0xffffffffu, cnt, o);
        if (tt == 0) atomicAdd(&g_inter, (unsigned long long)cnt);
    }
}

// -------------------- K3: X^T X Gram (uncentered) + column sums ------------
__global__ void k_xtx() {
    int rb = blockIdx.x * 8;   // gram row base (grid.x = 12)
    int ch = blockIdx.y;       // chunk (grid.y = 16)
    int t = threadIdx.x;       // 96

    float acc[8] = {0, 0, 0, 0, 0, 0, 0, 0};
    float colsum = 0.0f;
    int row0 = ch * 256;
    for (int i = 0; i < 256; i++) {
        const float* xrow = &g_X[(row0 + i) * DIMX];
        float xk = xrow[t];
        colsum += xk;
#pragma unroll
        for (int s = 0; s < 8; s++)
            acc[s] += xrow[rb + s] * xk;
    }
#pragma unroll
    for (int s = 0; s < 8; s++)
        atomicAdd(&g_S[(rb + s) * DIMX + t], acc[s]);
    if (blockIdx.x == 0) {
        if (ch < 8) atomicAdd(&g_sumP[t], (double)colsum);
        else        atomicAdd(&g_sumL[t], (double)colsum);
    }
}

// -------------------- K4: Chebyshev subspace (B=4) + Rayleigh-Ritz ---------
// Top-3 eigenspace of C = (S - n mu mu^T)/(n-1). Band [0,0.85], T5 per
// stage amplifies the top triple 17-67x vs <=1 in-band; 3 stages + CholQR
// each (ridge-guarded). B=4 columns: top-3 + 1 buffer. RR 4x4 resolves the
// near-degenerate triple.
__global__ void __launch_bounds__(EIG_THREADS)
k_eig(float* __restrict__ out) {
    extern __shared__ float esm[];
    float* C  = esm;            // 96 x 97 (padded)
    float* Y0 = C + 96 * 97;    // 96 x 4
    float* Y1 = Y0 + 96 * 4;    // 96 x 4
    float* P  = Y1 + 96 * 4;    // 4 x 96 x 4 partials
    __shared__ float S4[16], R4[16], Rinv[4], W4[16];
    __shared__ float T4[4 * 5], V4[4 * 5];
    __shared__ float rc2[2], rs2[2];
    __shared__ int   rp2[2], rq2[2];
    __shared__ float dvec[DIMX], mus[DIMX], gvec[4];

    const int t = threadIdx.x;
    const int r = t % 96;           // row
    const int g = t / 96;           // j-group 0..3

    if (t < DIMX) {
        double sp = g_sumP[t], sl = g_sumL[t];
        mus[t]  = (float)((sp + sl) / 4096.0);
        dvec[t] = (float)(sp / 2048.0 - sl / 2048.0);
    }
    __syncthreads();

    for (int idx = t; idx < 96 * 96; idx += EIG_THREADS) {
        int i = idx / 96, j = idx - i * 96;
        C[i * 97 + j] = (g_S[idx] - 4096.0f * mus[i] * mus[j]) * (1.0f / 4095.0f);
    }
    if (t < 96) {
#pragma unroll
        for (int s = 0; s < 4; s++)
            Y0[t * 4 + s] = cosf(0.7f * (float)((t + 1) * (s + 1))) +
                            ((t == s) ? 0.05f : 0.0f);
    }
    __syncthreads();

    float* cur = Y0;
    float* prv = Y1;

#define MATVEC(SRC)                                                       \
    {                                                                     \
        float a0=0,a1=0,a2=0,a3=0;                                        \
        int j0 = g * 24;                                                  \
        _Pragma("unroll 4")                                               \
        for (int jj = 0; jj < 24; jj++) {                                 \
            int j = j0 + jj;                                              \
            float c = C[r * 97 + j];                                      \
            float4 y = *(const float4*)&SRC[j * 4];                       \
            a0 += c * y.x; a1 += c * y.y; a2 += c * y.z; a3 += c * y.w;   \
        }                                                                 \
        *(float4*)&P[(g * 96 + r) * 4] = make_float4(a0, a1, a2, a3);     \
    }                                                                     \
    __syncthreads();

// 384 elements (96 rows x 4 cols), one per thread
#define REDUCE3(ca, cb, cc, CUR, PRV, DST)                                \
    {                                                                     \
        float cy = P[t] + P[384 + t] + P[768 + t] + P[1152 + t];          \
        DST[t] = (ca) * cy + (cb) * CUR[t] + (cc) * PRV[t];               \
    }                                                                     \
    __syncthreads();

#define REDUCE2(ca, cb, CUR, DST)                                         \
    {                                                                     \
        float cy = P[t] + P[384 + t] + P[768 + t] + P[1152 + t];          \
        DST[t] = (ca) * cy + (cb) * CUR[t];                               \
    }                                                                     \
    __syncthreads();

// 16 pairs x 4-way split over rows
#define GRAM4(SRC)                                                        \
    if (t < 64) {                                                         \
        int pair = t >> 2, sub = t & 3;                                   \
        int a = pair >> 2, b = pair & 3;                                  \
        float s = 0.0f;                                                   \
        for (int i = sub * 24; i < sub * 24 + 24; i++)                    \
            s += SRC[i * 4 + a] * SRC[i * 4 + b];                         \
        s += __shfl_down_sync(0xffffffffu, s, 1);                         \
        s += __shfl_down_sync(0xffffffffu, s, 2);                         \
        if (sub == 0) S4[pair] = s;                                       \
    }                                                                     \
    __syncthreads();

#define CHOL4()                                                           \
    if (t == 0) {                                                         \
        float tr = S4[0] + S4[5] + S4[10] + S4[15];                       \
        float ridge = 1e-6f * tr;                                         \
        _Pragma("unroll")                                                 \
        for (int k = 0; k < 4; k++) S4[k * 4 + k] += ridge;               \
        _Pragma("unroll")                                                 \
        for (int k = 0; k < 4; k++) {                                     \
            float dk = sqrtf(fmaxf(S4[k * 4 + k], 1e-30f));               \
            float inv = 1.0f / dk;                                        \
            R4[k * 4 + k] = dk; Rinv[k] = inv;                            \
            for (int j = k + 1; j < 4; j++)                               \
                R4[k * 4 + j] = S4[k * 4 + j] * inv;                      \
            for (int i = k + 1; i < 4; i++)                               \
                for (int j = i; j < 4; j++)                               \
                    S4[i * 4 + j] -= R4[k * 4 + i] * R4[k * 4 + j];       \
        }                                                                 \
    }                                                                     \
    __syncthreads();

#define RSOLVE(SRC, DST)                                                  \
    if (t < 96) {                                                         \
        float z[4], y[4];                                                 \
        _Pragma("unroll")                                                 \
        for (int s = 0; s < 4; s++) z[s] = SRC[t * 4 + s];                \
        _Pragma("unroll")                                                 \
        for (int s = 0; s < 4; s++) {                                     \
            float v = z[s];                                               \
            for (int k = 0; k < s; k++) v -= y[k] * R4[k * 4 + s];        \
            y[s] = v * Rinv[s];                                           \
        }                                                                 \
        _Pragma("unroll")                                                 \
        for (int s = 0; s < 4; s++) DST[t * 4 + s] = y[s];                \
    }                                                                     \
    __syncthreads();

    const float c1 = 2.0f / CHEB_B;   // init step:  Y1 = (2/b) C Y0 - Y0
    const float c4 = 4.0f / CHEB_B;   // recurrence: Yn = (4/b) C Yk - 2 Yk - Yp

    for (int stage = 0; stage < CHEB_STAGES; stage++) {
        MATVEC(cur);
        REDUCE2(c1, -1.0f, cur, prv);
        { float* tmp = cur; cur = prv; prv = tmp; }
        for (int k = 0; k < CHEB_DEG - 1; k++) {
            MATVEC(cur);
            REDUCE3(c4, -2.0f, -1.0f, cur, prv, prv);
            { float* tmp = cur; cur = prv; prv = tmp; }
        }
        GRAM4(cur);
        CHOL4();
        RSOLVE(cur, cur);
    }

    // Z = C*Y for Rayleigh-Ritz (Z lands in prv)
    MATVEC(cur);
    REDUCE2(1.0f, 0.0f, cur, prv);

    // W4 = cur' * prv
    if (t < 64) {
        int pair = t >> 2, sub = t & 3;
        int a = pair >> 2, b = pair & 3;
        float s = 0.0f;
        for (int i = sub * 24; i < sub * 24 + 24; i++)
            s += cur[i * 4 + a] * prv[i * 4 + b];
        s += __shfl_down_sync(0xffffffffu, s, 1);
        s += __shfl_down_sync(0xffffffffu, s, 2);
        if (sub == 0) W4[pair] = s;
    }
    __syncthreads();
    if (t < 16) {
        int a = t >> 2, b = t & 3;
        T4[a * 5 + b] = 0.5f * (W4[a * 4 + b] + W4[b * 4 + a]);
    }
    if (t >= 16 && t < 32) {
        int e = t - 16;
        int j = e >> 2, k = e & 3;
        V4[j * 5 + k] = (j == k) ? 1.0f : 0.0f;
    }
    __syncthreads();

    // g = Y' d (warp1, concurrent with warp0's Jacobi)
    if (t >= 32 && t < 36) {
        int a = t - 32;
        float s = 0.0f;
        for (int i = 0; i < 96; i++) s += cur[i * 4 + a] * dvec[i];
        gvec[a] = s;
    }

    // warp 0: 4x4 cyclic Jacobi with eigenvectors (tournament: 3 rounds/sweep)
    if (t < 32) {
        for (int sweep = 0; sweep < 6; sweep++) {
            for (int rr = 0; rr < 3; rr++) {
                if (t < 2) {
                    int p, q;
                    if (t == 0) { p = 3; q = rr; }
                    else { p = (rr + 1) % 3; q = (rr + 2) % 3; }
                    rp2[t] = p; rq2[t] = q;
                    float app = T4[p * 5 + p];
                    float aqq = T4[q * 5 + q];
                    float apq = T4[p * 5 + q];
                    float c = 1.0f, s = 0.0f;
                    if (fabsf(apq) > 1e-30f) {
                        float tau = (aqq - app) / (2.0f * apq);
                        float tt = (tau >= 0.0f)
                                       ? 1.0f / (tau + sqrtf(1.0f + tau * tau))
                                       : 1.0f / (tau - sqrtf(1.0f + tau * tau));
                        c = rsqrtf(1.0f + tt * tt);
                        s = tt * c;
                    }
                    rc2[t] = c; rs2[t] = s;
                }
                __syncwarp();
                if (t < 4) {   // T: 4 independent 2x2 block rotations
                    int a = t >> 1, b = t & 1;
                    int pa = rp2[a], qa = rq2[a];
                    int pb = rp2[b], qb = rq2[b];
                    float ca = rc2[a], sa = rs2[a];
                    float cb = rc2[b], sb = rs2[b];
                    float x00 = T4[pa * 5 + pb], x01 = T4[pa * 5 + qb];
                    float x10 = T4[qa * 5 + pb], x11 = T4[qa * 5 + qb];
                    float y00 = ca * x00 - sa * x10;
                    float y01 = ca * x01 - sa * x11;
                    float y10 = sa * x00 + ca * x10;
                    float y11 = sa * x01 + ca * x11;
                    T4[pa * 5 + pb] = cb * y00 - sb * y01;
                    T4[pa * 5 + qb] = sb * y00 + cb * y01;
                    T4[qa * 5 + pb] = cb * y10 - sb * y11;
                    T4[qa * 5 + qb] = sb * y10 + cb * y11;
                }
                if (t >= 8 && t < 16) {   // V: 4 rows x 2 pairs
                    int e = t - 8;
                    int j = e >> 1, k = e & 1;
                    int p = rp2[k], q = rq2[k];
                    float c = rc2[k], s = rs2[k];
                    float vp = V4[j * 5 + p], vq = V4[j * 5 + q];
                    V4[j * 5 + p] = c * vp - s * vq;
                    V4[j * 5 + q] = s * vp + c * vq;
                }
                __syncwarp();
            }
        }
    }
    __syncthreads();

    if (t == 0) {
        // top-3 of the 4 Ritz values = all but the smallest
        int imin = 0;
        float vmin = T4[0];
#pragma unroll
        for (int i = 1; i < 4; i++) {
            float e = T4[i * 5 + i];
            if (e < vmin) { vmin = e; imin = i; }
        }
        float ssum = 0.0f;
#pragma unroll
        for (int k = 0; k < 4; k++) {
            if (k == imin) continue;
            float pr = 0.0f;
            for (int a = 0; a < 4; a++) pr += V4[a * 5 + k] * gvec[a];
            ssum += pr * pr;
        }
        float sv2 = 0.0f;
        for (int v = 0; v < RES; v++) sv2 += g_sv[v] * g_sv[v];
        float dist_pca = sqrtf(sv2) * sqrtf(ssum);
        float pca_loss = 1.0f - dist_pca;

        float inter = (float)g_inter;
        float uni = 2048.0f - inter;   // reference: P + P - inter
        float iou_loss = 1.0f - inter / uni;

        out[0] = pca_loss + iou_loss;
    }
}

// -------------------- launcher --------------------
extern "C" void kernel_launch(void* const* d_in, const int* in_sizes, int n_in,
                              void* d_out, int out_size) {
    const float* pred  = (const float*)d_in[0];
    const float* label = (const float*)d_in[1];
    float* out = (float*)d_out;

    cudaFuncSetAttribute(k_eig, cudaFuncAttributeMaxDynamicSharedMemorySize,
                         EIG_SMEM);

    k_init<<<1, 256>>>();
    k_curves<<<512, 384>>>(pred, label);
    k_xtx<<<dim3(12, 16), 96>>>();
    k_eig<<<1, EIG_THREADS, EIG_SMEM>>>(out);
}

// round 12
// speedup vs baseline: 36.0661x; 1.2020x over previous
#include <cuda_runtime.h>
#include <math.h>

#define NJ   68
#define RES  32
#define NB   2048
#define DIMX 96
#define NBLK 64
#define NTHR 384
#define CHEB_B 0.85f
#define CHEB_DEG 5
#define CHEB_STAGES 3
// dyn smem (max over phases): phase2 C(96*97)+Y0(384)+Y1(384)+P(1536) floats
#define DSM_BYTES ((96 * 97 + 384 + 384 + 1536) * 4)

// -------------------- device globals (no allocs) --------------------
__device__ float g_X[2 * NB * DIMX];
__device__ float g_S[DIMX * DIMX];      // Gram, atomically accumulated
__device__ float g_colP[NBLK * DIMX];   // per-block column-sum partials
__device__ float g_colL[NBLK * DIMX];
__device__ int   g_cnt[NBLK];           // per-block IoU counts
__device__ int   g_bar1, g_bar2;        // spin barriers (reset at kernel end)

// compile-time knot vectors (match reference)
__device__ __host__ constexpr float knotU(int i) {
    return (i < 3) ? 0.0f : ((i >= 68) ? 1.0f : (float)((double)(i - 2) / 66.0));
}
__device__ __host__ constexpr float knotV(int i) {
    return (i < 4) ? 0.0f : ((i >= 68) ? 1.0f : (float)((double)(i - 3) / 65.0));
}

__global__ void __launch_bounds__(NTHR)
k_fused(const float* __restrict__ pred, const float* __restrict__ label,
        float* __restrict__ out) {
    extern __shared__ float dsm[];
    // phase 0/1a carve
    float* sNu = dsm;                    // 68*32 = 2176
    float* sPL = dsm + 2176;             // sP 4*204 | sL 4*204 = 1632
    float* cPL = dsm + 2176 + 1632;      // cP 4*96 | cL 4*96 = 768
    // phase 1b carve (reuses front)
    float* Xt  = dsm;                    // 32*96 = 3072
    // phase 2 carve
    float* C  = dsm;                     // 96*97
    float* Y0 = dsm + 96 * 97;           // 96*4
    float* Y1 = Y0 + 384;
    float* P  = Y1 + 384;                // 4*96*4

    __shared__ float sv_s[RES];
    __shared__ int   cnt_s;
    __shared__ float S4[16], R4[16], Rinv[4], W4[16];
    __shared__ float T4[4 * 5], V4[4 * 5];
    __shared__ float rc2[2], rs2[2];
    __shared__ int   rp2[2], rq2[2];
    __shared__ float dvec[DIMX], mus[DIMX], gvec[4];

    const int b = blockIdx.x;
    const int t = threadIdx.x;
    const int sub = t / 96;      // 0..3
    const int tt  = t - sub * 96;

    // ---------------- Phase 0: basis (warp 0) + zero g_S slice ----------------
    if (t < 144) g_S[b * 144 + t] = 0.0f;
    if (t == 0) cnt_s = 0;
    if (t < 32) {
        int uj = t;
        float u = (float)((double)uj / 31.0);
        {   // Nu (p=2), fully unrolled, same arithmetic as reference
            float N[70];
#pragma unroll
            for (int i = 0; i < 70; i++)
                N[i] = (knotU(i) <= u && u < knotU(i + 1)) ? 1.0f : 0.0f;
#pragma unroll
            for (int d = 1; d <= 2; d++) {
#pragma unroll
                for (int i = 0; i < 69; i++) {
                    if (i < 70 - d) {
                        const float ld = knotU(i + d) - knotU(i);
                        const float rd = knotU(i + d + 1) - knotU(i + 1);
                        float t1 = (ld == 0.0f) ? 0.0f : (u - knotU(i)) / ld * N[i];
                        float t2 = (rd == 0.0f) ? 0.0f : (knotU(i + d + 1) - u) / rd * N[i + 1];
                        N[i] = t1 + t2;
                    }
                }
            }
#pragma unroll
            for (int i = 0; i < NJ; i++) sNu[i * 32 + uj] = N[i];
        }
        {   // Nv (q=3) -> sv only
            float N[71];
#pragma unroll
            for (int i = 0; i < 71; i++)
                N[i] = (knotV(i) <= u && u < knotV(i + 1)) ? 1.0f : 0.0f;
#pragma unroll
            for (int d = 1; d <= 3; d++) {
#pragma unroll
                for (int i = 0; i < 70; i++) {
                    if (i < 71 - d) {
                        const float ld = knotV(i + d) - knotV(i);
                        const float rd = knotV(i + d + 1) - knotV(i + 1);
                        float t1 = (ld == 0.0f) ? 0.0f : (u - knotV(i)) / ld * N[i];
                        float t2 = (rd == 0.0f) ? 0.0f : (knotV(i + d + 1) - u) / rd * N[i + 1];
                        N[i] = t1 + t2;
                    }
                }
            }
            float s = 0.0f;
#pragma unroll
            for (int i = 0; i < NJ; i++) s += N[i];
            sv_s[uj] = s;
        }
    }
    __syncthreads();

    // ---------------- Phase 1a: 32 batches/block ----------------
    float colP_acc = 0.0f, colL_acc = 0.0f;
    const int u = tt / 3, c = tt - u * 3;
    for (int it = 0; it < 8; it++) {
        int batch = b * 32 + it * 4 + sub;
        for (int i = tt; i < 204; i += 96) {
            sPL[sub * 204 + i]       = pred[batch * 204 + i];
            sPL[816 + sub * 204 + i] = label[batch * 204 + i];
        }
        __syncthreads();
        float aP = 0.0f, aL = 0.0f;
#pragma unroll 4
        for (int i = 0; i < NJ; i++) {
            float w = sNu[i * 32 + u];
            aP += sPL[sub * 204 + i * 3 + c] * w;
            aL += sPL[816 + sub * 204 + i * 3 + c] * w;
        }
        g_X[batch * DIMX + tt]        = aP;
        g_X[(NB + batch) * DIMX + tt] = aL;
        cPL[sub * 96 + tt]       = aP;
        cPL[384 + sub * 96 + tt] = aL;
        colP_acc += aP;
        colL_acc += aL;
        __syncthreads();
        if (tt < 32) {   // warp-aligned per sub
            float p0 = cPL[sub * 96 + tt * 3], p1 = cPL[sub * 96 + tt * 3 + 1], p2 = cPL[sub * 96 + tt * 3 + 2];
            float l0 = cPL[384 + sub * 96 + tt * 3], l1 = cPL[384 + sub * 96 + tt * 3 + 1], l2 = cPL[384 + sub * 96 + tt * 3 + 2];
            int cnt = 0;
#pragma unroll
            for (int v = 0; v < RES; v++) {
                float sv = sv_s[v];
                float d0 = p0 * sv - l0 * sv;
                float d1 = p1 * sv - l1 * sv;
                float d2 = p2 * sv - l2 * sv;
                float s = (d0 * d0 + d1 * d1) + d2 * d2;
                cnt += (s < 0.25f) ? 1 : 0;
            }
#pragma unroll
            for (int o = 16; o > 0; o >>= 1)
                cnt += __shfl_down_sync(0xffffffffu, cnt, o);
            if (tt == 0) atomicAdd(&cnt_s, cnt);
        }
        __syncthreads();
    }
    // colsum partials: reduce 4 subs via shared
    cPL[sub * 96 + tt]       = colP_acc;
    cPL[384 + sub * 96 + tt] = colL_acc;
    __syncthreads();
    if (sub == 0) {
        g_colP[b * 96 + tt] = cPL[tt] + cPL[96 + tt] + cPL[192 + tt] + cPL[288 + tt];
        g_colL[b * 96 + tt] = cPL[384 + tt] + cPL[480 + tt] + cPL[576 + tt] + cPL[672 + tt];
    }
    if (t == 0) g_cnt[b] = cnt_s;

    // ---------------- Barrier 1 (full) ----------------
    __syncthreads();
    if (t == 0) {
        __threadfence();
        atomicAdd(&g_bar1, 1);
        while (atomicAdd(&g_bar1, 0) < NBLK) __nanosleep(100);
        __threadfence();
    }
    __syncthreads();

    // ---------------- Phase 1b: Gram, 64 rows/block, 6x4 thread tile ----------
    {
        const int ti = t / 24, tj = t - (t / 24) * 24;   // 16 x 24
        const int i0 = ti * 6, j0 = tj * 4;
        float acc[24];
#pragma unroll
        for (int k = 0; k < 24; k++) acc[k] = 0.0f;
        int r0 = b * 64;
        for (int st = 0; st < 2; st++) {
            const float4* src = (const float4*)&g_X[(r0 + st * 32) * DIMX];
            float4* dst = (float4*)Xt;
            for (int i = t; i < 768; i += NTHR) dst[i] = src[i];
            __syncthreads();
#pragma unroll 4
            for (int row = 0; row < 32; row++) {
                const float* xr = &Xt[row * 96];
                float2 A0 = *(const float2*)(xr + i0);
                float2 A1 = *(const float2*)(xr + i0 + 2);
                float2 A2 = *(const float2*)(xr + i0 + 4);
                float4 Bv = *(const float4*)(xr + j0);
                float xi[6] = {A0.x, A0.y, A1.x, A1.y, A2.x, A2.y};
                float xj[4] = {Bv.x, Bv.y, Bv.z, Bv.w};
#pragma unroll
                for (int a = 0; a < 6; a++)
#pragma unroll
                    for (int bb = 0; bb < 4; bb++)
                        acc[a * 4 + bb] += xi[a] * xj[bb];
            }
            __syncthreads();
        }
#pragma unroll
        for (int a = 0; a < 6; a++)
#pragma unroll
            for (int bb = 0; bb < 4; bb++)
                atomicAdd(&g_S[(i0 + a) * 96 + (j0 + bb)], acc[a * 4 + bb]);
    }

    // ---------------- Barrier 2 (arrive; block 0 waits) ----------------
    __syncthreads();
    if (t == 0) { __threadfence(); atomicAdd(&g_bar2, 1); }
    if (b != 0) return;
    if (t == 0) {
        while (atomicAdd(&g_bar2, 0) < NBLK) __nanosleep(100);
        __threadfence();
    }
    __syncthreads();

    // ---------------- Phase 2 (block 0 only): eig + finalize ----------------
    if (t < DIMX) {
        double sp = 0.0, sl = 0.0;
        for (int k = 0; k < NBLK; k++) {
            sp += (double)g_colP[k * 96 + t];
            sl += (double)g_colL[k * 96 + t];
        }
        mus[t]  = (float)((sp + sl) / 4096.0);
        dvec[t] = (float)(sp / 2048.0 - sl / 2048.0);
    }
    __syncthreads();
    for (int idx = t; idx < 96 * 96; idx += NTHR) {
        int i = idx / 96, j = idx - i * 96;
        C[i * 97 + j] = (g_S[idx] - 4096.0f * mus[i] * mus[j]) * (1.0f / 4095.0f);
    }
    if (t < 96) {
#pragma unroll
        for (int s = 0; s < 4; s++)
            Y0[t * 4 + s] = cosf(0.7f * (float)((t + 1) * (s + 1))) +
                            ((t == s) ? 0.05f : 0.0f);
    }
    __syncthreads();

    float* cur = Y0;
    float* prv = Y1;
    const int r = t % 96;
    const int g = t / 96;

#define MATVEC(SRC)                                                       \
    {                                                                     \
        float a0=0,a1=0,a2=0,a3=0;                                        \
        int j0_ = g * 24;                                                 \
        _Pragma("unroll 4")                                               \
        for (int jj = 0; jj < 24; jj++) {                                 \
            int j = j0_ + jj;                                             \
            float cc_ = C[r * 97 + j];                                    \
            float4 y = *(const float4*)&SRC[j * 4];                       \
            a0 += cc_ * y.x; a1 += cc_ * y.y; a2 += cc_ * y.z; a3 += cc_ * y.w; \
        }                                                                 \
        *(float4*)&P[(g * 96 + r) * 4] = make_float4(a0, a1, a2, a3);     \
    }                                                                     \
    __syncthreads();

#define REDUCE3(ca, cb, cc, CUR, PRV, DST)                                \
    {                                                                     \
        float cy = P[t] + P[384 + t] + P[768 + t] + P[1152 + t];          \
        DST[t] = (ca) * cy + (cb) * CUR[t] + (cc) * PRV[t];               \
    }                                                                     \
    __syncthreads();

#define REDUCE2(ca, cb, CUR, DST)                                         \
    {                                                                     \
        float cy = P[t] + P[384 + t] + P[768 + t] + P[1152 + t];          \
        DST[t] = (ca) * cy + (cb) * CUR[t];                               \
    }                                                                     \
    __syncthreads();

#define GRAM4(SRC)                                                        \
    if (t < 64) {                                                         \
        int pair = t >> 2, sb = t & 3;                                    \
        int a = pair >> 2, bb = pair & 3;                                 \
        float s = 0.0f;                                                   \
        for (int i = sb * 24; i < sb * 24 + 24; i++)                      \
            s += SRC[i * 4 + a] * SRC[i * 4 + bb];                        \
        s += __shfl_down_sync(0xffffffffu, s, 1);                         \
        s += __shfl_down_sync(0xffffffffu, s, 2);                         \
        if (sb == 0) S4[pair] = s;                                        \
    }                                                                     \
    __syncthreads();

#define CHOL4()                                                           \
    if (t == 0) {                                                         \
        float tr = S4[0] + S4[5] + S4[10] + S4[15];                       \
        float ridge = 1e-6f * tr;                                         \
        _Pragma("unroll")                                                 \
        for (int k = 0; k < 4; k++) S4[k * 4 + k] += ridge;               \
        _Pragma("unroll")                                                 \
        for (int k = 0; k < 4; k++) {                                     \
            float dk = sqrtf(fmaxf(S4[k * 4 + k], 1e-30f));               \
            float inv = 1.0f / dk;                                        \
            R4[k * 4 + k] = dk; Rinv[k] = inv;                            \
            for (int j = k + 1; j < 4; j++)                               \
                R4[k * 4 + j] = S4[k * 4 + j] * inv;                      \
            for (int i = k + 1; i < 4; i++)                               \
                for (int j = i; j < 4; j++)                               \
                    S4[i * 4 + j] -= R4[k * 4 + i] * R4[k * 4 + j];       \
        }                                                                 \
    }                                                                     \
    __syncthreads();

#define RSOLVE(SRC, DST)                                                  \
    if (t < 96) {                                                         \
        float z[4], y[4];                                                 \
        _Pragma("unroll")                                                 \
        for (int s = 0; s < 4; s++) z[s] = SRC[t * 4 + s];                \
        _Pragma("unroll")                                                 \
        for (int s = 0; s < 4; s++) {                                     \
            float v = z[s];                                               \
            for (int k = 0; k < s; k++) v -= y[k] * R4[k * 4 + s];        \
            y[s] = v * Rinv[s];                                           \
        }                                                                 \
        _Pragma("unroll")                                                 \
        for (int s = 0; s < 4; s++) DST[t * 4 + s] = y[s];                \
    }                                                                     \
    __syncthreads();

    const float c1 = 2.0f / CHEB_B;
    const float c4 = 4.0f / CHEB_B;

    for (int stage = 0; stage < CHEB_STAGES; stage++) {
        MATVEC(cur);
        REDUCE2(c1, -1.0f, cur, prv);
        { float* tmp = cur; cur = prv; prv = tmp; }
        for (int k = 0; k < CHEB_DEG - 1; k++) {
            MATVEC(cur);
            REDUCE3(c4, -2.0f, -1.0f, cur, prv, prv);
            { float* tmp = cur; cur = prv; prv = tmp; }
        }
        GRAM4(cur);
        CHOL4();
        RSOLVE(cur, cur);
    }

    MATVEC(cur);
    REDUCE2(1.0f, 0.0f, cur, prv);

    if (t < 64) {
        int pair = t >> 2, sb = t & 3;
        int a = pair >> 2, bb = pair & 3;
        float s = 0.0f;
        for (int i = sb * 24; i < sb * 24 + 24; i++)
            s += cur[i * 4 + a] * prv[i * 4 + bb];
        s += __shfl_down_sync(0xffffffffu, s, 1);
        s += __shfl_down_sync(0xffffffffu, s, 2);
        if (sb == 0) W4[pair] = s;
    }
    __syncthreads();
    if (t < 16) {
        int a = t >> 2, bb = t & 3;
        T4[a * 5 + bb] = 0.5f * (W4[a * 4 + bb] + W4[bb * 4 + a]);
    }
    if (t >= 16 && t < 32) {
        int e = t - 16;
        int j = e >> 2, k = e & 3;
        V4[j * 5 + k] = (j == k) ? 1.0f : 0.0f;
    }
    __syncthreads();

    if (t >= 32 && t < 36) {
        int a = t - 32;
        float s = 0.0f;
        for (int i = 0; i < 96; i++) s += cur[i * 4 + a] * dvec[i];
        gvec[a] = s;
    }

    if (t < 32) {
        for (int sweep = 0; sweep < 6; sweep++) {
            for (int rr = 0; rr < 3; rr++) {
                if (t < 2) {
                    int p, q;
                    if (t == 0) { p = 3; q = rr; }
                    else { p = (rr + 1) % 3; q = (rr + 2) % 3; }
                    rp2[t] = p; rq2[t] = q;
                    float app = T4[p * 5 + p];
                    float aqq = T4[q * 5 + q];
                    float apq = T4[p * 5 + q];
                    float cc_ = 1.0f, ss_ = 0.0f;
                    if (fabsf(apq) > 1e-30f) {
                        float tau = (aqq - app) / (2.0f * apq);
                        float tv = (tau >= 0.0f)
                                       ? 1.0f / (tau + sqrtf(1.0f + tau * tau))
                                       : 1.0f / (tau - sqrtf(1.0f + tau * tau));
                        cc_ = rsqrtf(1.0f + tv * tv);
                        ss_ = tv * cc_;
                    }
                    rc2[t] = cc_; rs2[t] = ss_;
                }
                __syncwarp();
                if (t < 4) {
                    int a = t >> 1, bb = t & 1;
                    int pa = rp2[a], qa = rq2[a];
                    int pb = rp2[bb], qb = rq2[bb];
                    float ca = rc2[a], sa = rs2[a];
                    float cb2 = rc2[bb], sb2 = rs2[bb];
                    float x00 = T4[pa * 5 + pb], x01 = T4[pa * 5 + qb];
                    float x10 = T4[qa * 5 + pb], x11 = T4[qa * 5 + qb];
                    float y00 = ca * x00 - sa * x10;
                    float y01 = ca * x01 - sa * x11;
                    float y10 = sa * x00 + ca * x10;
                    float y11 = sa * x01 + ca * x11;
                    T4[pa * 5 + pb] = cb2 * y00 - sb2 * y01;
                    T4[pa * 5 + qb] = sb2 * y00 + cb2 * y01;
                    T4[qa * 5 + pb] = cb2 * y10 - sb2 * y11;
                    T4[qa * 5 + qb] = sb2 * y10 + cb2 * y11;
                }
                if (t >= 8 && t < 16) {
                    int e = t - 8;
                    int j = e >> 1, k = e & 1;
                    int p = rp2[k], q = rq2[k];
                    float cc_ = rc2[k], ss_ = rs2[k];
                    float vp = V4[j * 5 + p], vq = V4[j * 5 + q];
                    V4[j * 5 + p] = cc_ * vp - ss_ * vq;
                    V4[j * 5 + q] = ss_ * vp + cc_ * vq;
                }
                __syncwarp();
            }
        }
    }
    __syncthreads();

    if (t == 0) {
        int imin = 0;
        float vmin = T4[0];
#pragma unroll
        for (int i = 1; i < 4; i++) {
            float e = T4[i * 5 + i];
            if (e < vmin) { vmin = e; imin = i; }
        }
        float ssum = 0.0f;
#pragma unroll
        for (int k = 0; k < 4; k++) {
            if (k == imin) continue;
            float pr = 0.0f;
            for (int a = 0; a < 4; a++) pr += V4[a * 5 + k] * gvec[a];
            ssum += pr * pr;
        }
        float sv2 = 0.0f;
        for (int v = 0; v < RES; v++) sv2 += sv_s[v] * sv_s[v];
        float dist_pca = sqrtf(sv2) * sqrtf(ssum);
        float pca_loss = 1.0f - dist_pca;

        int icnt = 0;
        for (int k = 0; k < NBLK; k++) icnt += g_cnt[k];
        float inter = (float)icnt;
        float uni = 2048.0f - inter;   // reference: P + P - inter
        float iou_loss = 1.0f - inter / uni;

        out[0] = pca_loss + iou_loss;

        // reset barriers for next graph replay (block 0 is last to finish)
        atomicExch(&g_bar1, 0);
        atomicExch(&g_bar2, 0);
    }
}

// -------------------- launcher --------------------
extern "C" void kernel_launch(void* const* d_in, const int* in_sizes, int n_in,
                              void* d_out, int out_size) {
    const float* pred  = (const float*)d_in[0];
    const float* label = (const float*)d_in[1];
    float* out = (float*)d_out;

    cudaFuncSetAttribute(k_fused, cudaFuncAttributeMaxDynamicSharedMemorySize,
                         DSM_BYTES);
    k_fused<<<NBLK, NTHR, DSM_BYTES>>>(pred, label, out);
}